// round 1
// baseline (speedup 1.0000x reference)
#include <cuda_runtime.h>
#include <cuda_bf16.h>
#include <stdint.h>

#define HIDDEN 768
#define INNER  512
#define MAXM   32768

#define BM 128
#define BN 128
#define BK 32
#define SSTR 40                    // bf16 elems per smem row (32 + 8 pad, keeps ldmatrix conflict-free)
#define STAGE_ELEMS (BM * SSTR)    // 5120 bf16 per matrix-half per stage
#define SMEM_BYTES (8 * STAGE_ELEMS * 2)  // 2 stages * 4 arrays(Ah,Al,Bh,Bl) = 81920 B

// -------- device scratch (allocation-free rule: __device__ globals) --------
__device__ float g_h[(size_t)MAXM * INNER];        // 64 MB
__device__ float g_pred[(size_t)MAXM * HIDDEN];    // 96 MB
__device__ __nv_bfloat16 g_w1h[INNER * HIDDEN];
__device__ __nv_bfloat16 g_w1l[INNER * HIDDEN];
__device__ __nv_bfloat16 g_w2h[HIDDEN * INNER];
__device__ __nv_bfloat16 g_w2l[HIDDEN * INNER];
__device__ __nv_bfloat16 g_woh[HIDDEN * HIDDEN];
__device__ __nv_bfloat16 g_wol[HIDDEN * HIDDEN];

// -------- helpers --------
__device__ __forceinline__ uint32_t sptr(const void* p) {
    return (uint32_t)__cvta_generic_to_shared(const_cast<void*>(p));
}

__device__ __forceinline__ void ldsm4(uint32_t& d0, uint32_t& d1, uint32_t& d2, uint32_t& d3,
                                      uint32_t addr) {
    asm volatile("ldmatrix.sync.aligned.m8n8.x4.shared.b16 {%0,%1,%2,%3}, [%4];"
                 : "=r"(d0), "=r"(d1), "=r"(d2), "=r"(d3) : "r"(addr));
}

__device__ __forceinline__ void mma16816(float c[4], const uint32_t a[4], const uint32_t b[2]) {
    asm volatile(
        "mma.sync.aligned.m16n8k16.row.col.f32.bf16.bf16.f32 "
        "{%0,%1,%2,%3}, {%4,%5,%6,%7}, {%8,%9}, {%0,%1,%2,%3};"
        : "+f"(c[0]), "+f"(c[1]), "+f"(c[2]), "+f"(c[3])
        : "r"(a[0]), "r"(a[1]), "r"(a[2]), "r"(a[3]), "r"(b[0]), "r"(b[1]));
}

// split fp32 pair -> packed bf16x2 hi and lo (hi = rn(v), lo = rn(v - hi))
__device__ __forceinline__ void split2(float a, float b, uint32_t& hi, uint32_t& lo) {
    __nv_bfloat16 ha = __float2bfloat16_rn(a);
    __nv_bfloat16 hb = __float2bfloat16_rn(b);
    __nv_bfloat16 la = __float2bfloat16_rn(a - __bfloat162float(ha));
    __nv_bfloat16 lb = __float2bfloat16_rn(b - __bfloat162float(hb));
    hi = ((uint32_t)__bfloat16_as_ushort(hb) << 16) | (uint32_t)__bfloat16_as_ushort(ha);
    lo = ((uint32_t)__bfloat16_as_ushort(lb) << 16) | (uint32_t)__bfloat16_as_ushort(la);
}

// -------- weight split --------
__global__ void split_w_kernel(const float* __restrict__ w,
                               __nv_bfloat16* __restrict__ hi,
                               __nv_bfloat16* __restrict__ lo, int n) {
    int i = blockIdx.x * blockDim.x + threadIdx.x;
    if (i >= n) return;
    float v = w[i];
    __nv_bfloat16 h = __float2bfloat16_rn(v);
    hi[i] = h;
    lo[i] = __float2bfloat16_rn(v - __bfloat162float(h));
}

// -------- GEMM: C[M,N] = A[M,K](fp32, split on the fly) @ B[N,K]^T (pre-split bf16) + bias --------
template <bool RELU>
__global__ void __launch_bounds__(256, 1)
gemm_split(const float* __restrict__ A,
           const __nv_bfloat16* __restrict__ Bh,
           const __nv_bfloat16* __restrict__ Bl,
           const float* __restrict__ bias,
           float* __restrict__ C,
           int M, int N, int K) {
    extern __shared__ __nv_bfloat16 smem[];
    __nv_bfloat16* sAh = smem;
    __nv_bfloat16* sAl = smem + 2 * STAGE_ELEMS;
    __nv_bfloat16* sBh = smem + 4 * STAGE_ELEMS;
    __nv_bfloat16* sBl = smem + 6 * STAGE_ELEMS;

    const int tid  = threadIdx.x;
    const int lane = tid & 31;
    const int warp = tid >> 5;
    const int m0 = blockIdx.y * BM;
    const int n0 = blockIdx.x * BN;
    const int wm = (warp >> 2) * 64;  // 2 warp rows (M)
    const int wn = (warp & 3) * 32;   // 4 warp cols (N)

    // global load mapping
    const int ar = tid >> 3;        // A row within tile (x4 iterations of +32)
    const int ac = (tid & 7) * 4;   // A col (float4)
    const int br = tid >> 2;        // B row (x2 iterations of +64)
    const int bc = (tid & 3) * 8;   // B col (8 bf16 = 16B chunk)

    float acc[4][4][4];
#pragma unroll
    for (int i = 0; i < 4; i++)
#pragma unroll
        for (int j = 0; j < 4; j++)
#pragma unroll
            for (int r = 0; r < 4; r++) acc[i][j][r] = 0.f;

    const float* Ag = A + (size_t)m0 * K;
    const __nv_bfloat16* Bhg = Bh + (size_t)n0 * K;
    const __nv_bfloat16* Blg = Bl + (size_t)n0 * K;
    const int Ksteps = K / BK;

    // ---- prologue: fill stage 0 ----
    {
#pragma unroll
        for (int i = 0; i < 4; i++) {
            float4 v = *reinterpret_cast<const float4*>(Ag + (size_t)(ar + i * 32) * K + ac);
            uint32_t h0, l0, h1, l1;
            split2(v.x, v.y, h0, l0);
            split2(v.z, v.w, h1, l1);
            *reinterpret_cast<uint2*>(sAh + (ar + i * 32) * SSTR + ac) = make_uint2(h0, h1);
            *reinterpret_cast<uint2*>(sAl + (ar + i * 32) * SSTR + ac) = make_uint2(l0, l1);
        }
#pragma unroll
        for (int i = 0; i < 2; i++) {
            int r = br + i * 64;
            *reinterpret_cast<uint4*>(sBh + r * SSTR + bc) =
                *reinterpret_cast<const uint4*>(Bhg + (size_t)r * K + bc);
            *reinterpret_cast<uint4*>(sBl + r * SSTR + bc) =
                *reinterpret_cast<const uint4*>(Blg + (size_t)r * K + bc);
        }
    }
    __syncthreads();

    // ldmatrix lane addressing
    const int a_row = wm + ((lane >> 3) & 1) * 8 + (lane & 7);
    const int a_kh  = ((lane >> 4) & 1) * 8;
    const int b_row = wn + ((lane >> 4) & 1) * 8 + (lane & 7);
    const int b_kh  = ((lane >> 3) & 1) * 8;

    int stage = 0;
    for (int ks = 0; ks < Ksteps; ++ks) {
        const bool pf = (ks + 1) < Ksteps;
        float4 av[4];
        uint4 bhv[2], blv[2];
        if (pf) {
            const int ko = (ks + 1) * BK;
#pragma unroll
            for (int i = 0; i < 4; i++)
                av[i] = *reinterpret_cast<const float4*>(Ag + (size_t)(ar + i * 32) * K + ko + ac);
#pragma unroll
            for (int i = 0; i < 2; i++) {
                int r = br + i * 64;
                bhv[i] = *reinterpret_cast<const uint4*>(Bhg + (size_t)r * K + ko + bc);
                blv[i] = *reinterpret_cast<const uint4*>(Blg + (size_t)r * K + ko + bc);
            }
        }

        const __nv_bfloat16* pAh = sAh + stage * STAGE_ELEMS;
        const __nv_bfloat16* pAl = sAl + stage * STAGE_ELEMS;
        const __nv_bfloat16* pBh = sBh + stage * STAGE_ELEMS;
        const __nv_bfloat16* pBl = sBl + stage * STAGE_ELEMS;

#pragma unroll
        for (int kk = 0; kk < 2; ++kk) {
            const int kc = kk * 16;
            uint32_t a[4][4], bh[4][2], bl[4][2];
#pragma unroll
            for (int i = 0; i < 4; i++)
                ldsm4(a[i][0], a[i][1], a[i][2], a[i][3],
                      sptr(pAh + (a_row + i * 16) * SSTR + kc + a_kh));
#pragma unroll
            for (int j = 0; j < 2; j++) {
                ldsm4(bh[2 * j][0], bh[2 * j][1], bh[2 * j + 1][0], bh[2 * j + 1][1],
                      sptr(pBh + (b_row + j * 16) * SSTR + kc + b_kh));
                ldsm4(bl[2 * j][0], bl[2 * j][1], bl[2 * j + 1][0], bl[2 * j + 1][1],
                      sptr(pBl + (b_row + j * 16) * SSTR + kc + b_kh));
            }
            // Ah*Bh
#pragma unroll
            for (int i = 0; i < 4; i++)
#pragma unroll
                for (int j = 0; j < 4; j++) mma16816(acc[i][j], a[i], bh[j]);
            // Ah*Bl
#pragma unroll
            for (int i = 0; i < 4; i++)
#pragma unroll
                for (int j = 0; j < 4; j++) mma16816(acc[i][j], a[i], bl[j]);
            // Al*Bh
#pragma unroll
            for (int i = 0; i < 4; i++)
                ldsm4(a[i][0], a[i][1], a[i][2], a[i][3],
                      sptr(pAl + (a_row + i * 16) * SSTR + kc + a_kh));
#pragma unroll
            for (int i = 0; i < 4; i++)
#pragma unroll
                for (int j = 0; j < 4; j++) mma16816(acc[i][j], a[i], bh[j]);
        }

        if (pf) {
            const int ns = stage ^ 1;
#pragma unroll
            for (int i = 0; i < 4; i++) {
                uint32_t h0, l0, h1, l1;
                split2(av[i].x, av[i].y, h0, l0);
                split2(av[i].z, av[i].w, h1, l1);
                *reinterpret_cast<uint2*>(sAh + ns * STAGE_ELEMS + (ar + i * 32) * SSTR + ac) =
                    make_uint2(h0, h1);
                *reinterpret_cast<uint2*>(sAl + ns * STAGE_ELEMS + (ar + i * 32) * SSTR + ac) =
                    make_uint2(l0, l1);
            }
#pragma unroll
            for (int i = 0; i < 2; i++) {
                int r = br + i * 64;
                *reinterpret_cast<uint4*>(sBh + ns * STAGE_ELEMS + r * SSTR + bc) = bhv[i];
                *reinterpret_cast<uint4*>(sBl + ns * STAGE_ELEMS + r * SSTR + bc) = blv[i];
            }
        }
        __syncthreads();
        stage ^= 1;
    }

    // ---- epilogue ----
    const int erow = lane >> 2;
    const int ecol = (lane & 3) * 2;
#pragma unroll
    for (int i = 0; i < 4; i++) {
#pragma unroll
        for (int j = 0; j < 4; j++) {
            const int col = n0 + wn + j * 8 + ecol;
            const float bv0 = __ldg(bias + col);
            const float bv1 = __ldg(bias + col + 1);
            const int row0 = m0 + wm + i * 16 + erow;
            float v0 = acc[i][j][0] + bv0;
            float v1 = acc[i][j][1] + bv1;
            float v2 = acc[i][j][2] + bv0;
            float v3 = acc[i][j][3] + bv1;
            if (RELU) {
                v0 = fmaxf(v0, 0.f); v1 = fmaxf(v1, 0.f);
                v2 = fmaxf(v2, 0.f); v3 = fmaxf(v3, 0.f);
            }
            *reinterpret_cast<float2*>(C + (size_t)row0 * N + col) = make_float2(v0, v1);
            *reinterpret_cast<float2*>(C + (size_t)(row0 + 8) * N + col) = make_float2(v2, v3);
        }
    }
}

// -------- LayerNorm over rows of 768, in place on d_out --------
__global__ void __launch_bounds__(256)
ln_kernel(float* __restrict__ out,
          const float* __restrict__ gamma,
          const float* __restrict__ beta) {
    const int row = blockIdx.x;
    float* p = out + (size_t)row * HIDDEN;
    float v[3];
    float s = 0.f, s2 = 0.f;
#pragma unroll
    for (int i = 0; i < 3; i++) {
        v[i] = p[threadIdx.x + i * 256];
        s += v[i];
        s2 += v[i] * v[i];
    }
#pragma unroll
    for (int o = 16; o > 0; o >>= 1) {
        s += __shfl_xor_sync(0xffffffffu, s, o);
        s2 += __shfl_xor_sync(0xffffffffu, s2, o);
    }
    __shared__ float ss[8], ss2[8];
    if ((threadIdx.x & 31) == 0) {
        ss[threadIdx.x >> 5] = s;
        ss2[threadIdx.x >> 5] = s2;
    }
    __syncthreads();
    float st = 0.f, st2 = 0.f;
#pragma unroll
    for (int i = 0; i < 8; i++) { st += ss[i]; st2 += ss2[i]; }
    const float mu = st * (1.0f / HIDDEN);
    const float var = st2 * (1.0f / HIDDEN) - mu * mu;
    const float inv = rsqrtf(var + 1e-5f);
#pragma unroll
    for (int i = 0; i < 3; i++) {
        const int c = threadIdx.x + i * 256;
        p[c] = (v[i] - mu) * inv * __ldg(gamma + c) + __ldg(beta + c);
    }
}

// -------- launch --------
extern "C" void kernel_launch(void* const* d_in, const int* in_sizes, int n_in,
                              void* d_out, int out_size) {
    const float* x     = (const float*)d_in[0];
    const float* W1    = (const float*)d_in[1];
    const float* b1    = (const float*)d_in[2];
    const float* W2    = (const float*)d_in[3];
    const float* b2    = (const float*)d_in[4];
    const float* Wo    = (const float*)d_in[5];
    const float* bo    = (const float*)d_in[6];
    const float* gamma = (const float*)d_in[7];
    const float* beta  = (const float*)d_in[8];
    float* out = (float*)d_out;
    (void)n_in; (void)out_size;

    const int M = in_sizes[0] / HIDDEN;  // 32768

    void *p_h, *p_pred, *p_w1h, *p_w1l, *p_w2h, *p_w2l, *p_woh, *p_wol;
    cudaGetSymbolAddress(&p_h, g_h);
    cudaGetSymbolAddress(&p_pred, g_pred);
    cudaGetSymbolAddress(&p_w1h, g_w1h);
    cudaGetSymbolAddress(&p_w1l, g_w1l);
    cudaGetSymbolAddress(&p_w2h, g_w2h);
    cudaGetSymbolAddress(&p_w2l, g_w2l);
    cudaGetSymbolAddress(&p_woh, g_woh);
    cudaGetSymbolAddress(&p_wol, g_wol);

    cudaFuncSetAttribute(gemm_split<true>, cudaFuncAttributeMaxDynamicSharedMemorySize, SMEM_BYTES);
    cudaFuncSetAttribute(gemm_split<false>, cudaFuncAttributeMaxDynamicSharedMemorySize, SMEM_BYTES);

    // split weights
    split_w_kernel<<<(INNER * HIDDEN + 255) / 256, 256>>>(
        W1, (__nv_bfloat16*)p_w1h, (__nv_bfloat16*)p_w1l, INNER * HIDDEN);
    split_w_kernel<<<(HIDDEN * INNER + 255) / 256, 256>>>(
        W2, (__nv_bfloat16*)p_w2h, (__nv_bfloat16*)p_w2l, HIDDEN * INNER);
    split_w_kernel<<<(HIDDEN * HIDDEN + 255) / 256, 256>>>(
        Wo, (__nv_bfloat16*)p_woh, (__nv_bfloat16*)p_wol, HIDDEN * HIDDEN);

    // GEMM1: h = relu(x @ W1^T + b1)
    gemm_split<true><<<dim3(INNER / BN, M / BM), 256, SMEM_BYTES>>>(
        x, (const __nv_bfloat16*)p_w1h, (const __nv_bfloat16*)p_w1l, b1,
        (float*)p_h, M, INNER, HIDDEN);

    // GEMM2: pred = h @ W2^T + b2
    gemm_split<false><<<dim3(HIDDEN / BN, M / BM), 256, SMEM_BYTES>>>(
        (const float*)p_h, (const __nv_bfloat16*)p_w2h, (const __nv_bfloat16*)p_w2l, b2,
        (float*)p_pred, M, HIDDEN, INNER);

    // GEMM3: out_preLN = pred @ Wo^T + bo   (written into d_out)
    gemm_split<false><<<dim3(HIDDEN / BN, M / BM), 256, SMEM_BYTES>>>(
        (const float*)p_pred, (const __nv_bfloat16*)p_woh, (const __nv_bfloat16*)p_wol, bo,
        out, M, HIDDEN, HIDDEN);

    // LayerNorm in place
    ln_kernel<<<M, 256>>>(out, gamma, beta);
}

// round 3
// speedup vs baseline: 1.3081x; 1.3081x over previous
#include <cuda_runtime.h>
#include <cuda_fp16.h>
#include <stdint.h>

#define HIDDEN 768
#define INNER  512
#define MAXM   32768

#define BM 128
#define BN 256
#define BK 32
#define ASTR 80                    // bytes per K-row in smem (64 data + 16 pad)
#define STG_A (BM * ASTR)          // 10240
#define STG_B (BN * ASTR)          // 20480
#define STGB (2 * STG_A + STG_B)   // 40960 per stage
#define NSTAGE 4
#define SMEM_TOTAL (NSTAGE * STGB) // 163840

// ---------------- device scratch (allocation-free rule) ----------------
__device__ __half g_xh[(size_t)MAXM * HIDDEN];
__device__ __half g_xl[(size_t)MAXM * HIDDEN];
__device__ __half g_hh[(size_t)MAXM * INNER];
__device__ __half g_hl[(size_t)MAXM * INNER];
__device__ __half g_ph[(size_t)MAXM * HIDDEN];
__device__ __half g_pl[(size_t)MAXM * HIDDEN];
__device__ __half g_w1[INNER * HIDDEN];
__device__ __half g_w2[HIDDEN * INNER];
__device__ __half g_wo[HIDDEN * HIDDEN];

// ---------------- helpers ----------------
__device__ __forceinline__ uint32_t s2u(const void* p) {
    uint32_t a;
    asm("{ .reg .u64 t; cvta.to.shared.u64 t, %1; cvt.u32.u64 %0, t; }" : "=r"(a) : "l"(p));
    return a;
}

__device__ __forceinline__ void ldsm4(uint32_t& d0, uint32_t& d1, uint32_t& d2, uint32_t& d3,
                                      uint32_t addr) {
    asm volatile("ldmatrix.sync.aligned.m8n8.x4.shared.b16 {%0,%1,%2,%3}, [%4];"
                 : "=r"(d0), "=r"(d1), "=r"(d2), "=r"(d3) : "r"(addr));
}

__device__ __forceinline__ void mma_h(float c[4], const uint32_t a[4], const uint32_t b[2]) {
    asm volatile(
        "mma.sync.aligned.m16n8k16.row.col.f32.f16.f16.f32 "
        "{%0,%1,%2,%3}, {%4,%5,%6,%7}, {%8,%9}, {%0,%1,%2,%3};"
        : "+f"(c[0]), "+f"(c[1]), "+f"(c[2]), "+f"(c[3])
        : "r"(a[0]), "r"(a[1]), "r"(a[2]), "r"(a[3]), "r"(b[0]), "r"(b[1]));
}

__device__ __forceinline__ void cpa(uint32_t dst, const void* src) {
    asm volatile("cp.async.cg.shared.global [%0], [%1], 16;" :: "r"(dst), "l"(src));
}
__device__ __forceinline__ void cp_commit() { asm volatile("cp.async.commit_group;"); }
template <int N> __device__ __forceinline__ void cp_wait() {
    asm volatile("cp.async.wait_group %0;" :: "n"(N));
}

// ---------------- conversions ----------------
// x -> fp16 hi/lo pair
__global__ void splitx_kernel(const float* __restrict__ x,
                              __half* __restrict__ hi, __half* __restrict__ lo, int n4) {
    int i = blockIdx.x * blockDim.x + threadIdx.x;
    if (i >= n4) return;
    float4 v = *reinterpret_cast<const float4*>(x + (size_t)i * 4);
    __half2 h01 = __floats2half2_rn(v.x, v.y);
    __half2 h23 = __floats2half2_rn(v.z, v.w);
    __half2 l01 = __floats2half2_rn(v.x - __low2float(h01), v.y - __high2float(h01));
    __half2 l23 = __floats2half2_rn(v.z - __low2float(h23), v.w - __high2float(h23));
    reinterpret_cast<__half2*>(hi)[2 * i]     = h01;
    reinterpret_cast<__half2*>(hi)[2 * i + 1] = h23;
    reinterpret_cast<__half2*>(lo)[2 * i]     = l01;
    reinterpret_cast<__half2*>(lo)[2 * i + 1] = l23;
}

// weights -> single fp16
__global__ void convw_kernel(const float* __restrict__ w, __half* __restrict__ o, int n4) {
    int i = blockIdx.x * blockDim.x + threadIdx.x;
    if (i >= n4) return;
    float4 v = *reinterpret_cast<const float4*>(w + (size_t)i * 4);
    reinterpret_cast<__half2*>(o)[2 * i]     = __floats2half2_rn(v.x, v.y);
    reinterpret_cast<__half2*>(o)[2 * i + 1] = __floats2half2_rn(v.z, v.w);
}

// ---------------- GEMM: C[M,N] = (Ah+Al)[M,K] @ B[N,K]^T + bias ----------------
// CTA 128x256, 8 warps (2x4 of 64x64), BK=32, 4-stage cp.async.
// EPI: 0 = relu + fp16 hi/lo out, 1 = fp16 hi/lo out, 2 = fp32 out
template <int EPI>
__global__ void __launch_bounds__(256, 1)
gemm_h2(const __half* __restrict__ Ah, const __half* __restrict__ Al,
        const __half* __restrict__ B, const float* __restrict__ bias,
        float* __restrict__ Co, __half* __restrict__ Ch, __half* __restrict__ Cl,
        int N, int K) {
    extern __shared__ __align__(128) char smem[];
    const uint32_t sb = s2u(smem);
    const int tid = threadIdx.x, lane = tid & 31, warp = tid >> 5;
    const int m0 = blockIdx.y * BM, n0 = blockIdx.x * BN;
    const int wm = (warp >> 2) * 64;   // 2 warp rows (M)
    const int wn = (warp & 3) * 64;    // 4 warp cols (N)

    const __half* Agh = Ah + (size_t)m0 * K;
    const __half* Agl = Al + (size_t)m0 * K;
    const __half* Bg  = B + (size_t)n0 * K;
    const int T = K / BK;

    float acc[4][8][4];
#pragma unroll
    for (int i = 0; i < 4; i++)
#pragma unroll
        for (int j = 0; j < 8; j++)
#pragma unroll
            for (int r = 0; r < 4; r++) acc[i][j][r] = 0.f;

    auto load_stage = [&](int s, int t) {
        const uint32_t so = sb + s * STGB;
        const int k0 = t * BK;
#pragma unroll
        for (int it = 0; it < 2; it++) {
            int idx = tid + it * 256;
            int r = idx >> 2, c = idx & 3;
            cpa(so + r * ASTR + c * 16,
                (const char*)(Agh + (size_t)r * K + k0) + c * 16);
            cpa(so + STG_A + r * ASTR + c * 16,
                (const char*)(Agl + (size_t)r * K + k0) + c * 16);
        }
#pragma unroll
        for (int it = 0; it < 4; it++) {
            int idx = tid + it * 256;
            int r = idx >> 2, c = idx & 3;
            cpa(so + 2 * STG_A + r * ASTR + c * 16,
                (const char*)(Bg + (size_t)r * K + k0) + c * 16);
        }
        cp_commit();
    };

    load_stage(0, 0);
    load_stage(1, 1);
    load_stage(2, 2);

    // ldmatrix lane addressing (proven mapping from R1)
    const int a_row = wm + ((lane >> 3) & 1) * 8 + (lane & 7);
    const int a_kh  = ((lane >> 4) & 1) * 8;
    const int b_row = wn + ((lane >> 4) & 1) * 8 + (lane & 7);
    const int b_kh  = ((lane >> 3) & 1) * 8;

    for (int t = 0; t < T; t++) {
        if (t <= T - 3) cp_wait<2>();
        else if (t == T - 2) cp_wait<1>();
        else cp_wait<0>();
        __syncthreads();
        if (t + 3 < T) load_stage((t + 3) & 3, t + 3);

        const uint32_t so = sb + (t & 3) * STGB;
#pragma unroll
        for (int kk = 0; kk < 2; kk++) {
            const int kc = kk * 16;
            uint32_t b[8][2];
#pragma unroll
            for (int j2 = 0; j2 < 4; j2++)
                ldsm4(b[2 * j2][0], b[2 * j2][1], b[2 * j2 + 1][0], b[2 * j2 + 1][1],
                      so + 2 * STG_A + (b_row + j2 * 16) * ASTR + (kc + b_kh) * 2);
            uint32_t a[4][4];
#pragma unroll
            for (int i = 0; i < 4; i++)
                ldsm4(a[i][0], a[i][1], a[i][2], a[i][3],
                      so + (a_row + i * 16) * ASTR + (kc + a_kh) * 2);
#pragma unroll
            for (int i = 0; i < 4; i++)
#pragma unroll
                for (int j = 0; j < 8; j++) mma_h(acc[i][j], a[i], b[j]);
#pragma unroll
            for (int i = 0; i < 4; i++)
                ldsm4(a[i][0], a[i][1], a[i][2], a[i][3],
                      so + STG_A + (a_row + i * 16) * ASTR + (kc + a_kh) * 2);
#pragma unroll
            for (int i = 0; i < 4; i++)
#pragma unroll
                for (int j = 0; j < 8; j++) mma_h(acc[i][j], a[i], b[j]);
        }
    }

    // ---- epilogue ----
    const int erow = lane >> 2;
    const int ecol = (lane & 3) * 2;
#pragma unroll
    for (int i = 0; i < 4; i++) {
        const int r0 = m0 + wm + i * 16 + erow;
#pragma unroll
        for (int j = 0; j < 8; j++) {
            const int col = n0 + wn + j * 8 + ecol;
            const float bv0 = __ldg(bias + col);
            const float bv1 = __ldg(bias + col + 1);
            float v0 = acc[i][j][0] + bv0;
            float v1 = acc[i][j][1] + bv1;
            float v2 = acc[i][j][2] + bv0;
            float v3 = acc[i][j][3] + bv1;
            if (EPI == 0) {
                v0 = fmaxf(v0, 0.f); v1 = fmaxf(v1, 0.f);
                v2 = fmaxf(v2, 0.f); v3 = fmaxf(v3, 0.f);
            }
            if (EPI == 2) {
                *reinterpret_cast<float2*>(Co + (size_t)r0 * N + col) = make_float2(v0, v1);
                *reinterpret_cast<float2*>(Co + (size_t)(r0 + 8) * N + col) = make_float2(v2, v3);
            } else {
                __half2 h01 = __floats2half2_rn(v0, v1);
                __half2 l01 = __floats2half2_rn(v0 - __low2float(h01), v1 - __high2float(h01));
                __half2 h23 = __floats2half2_rn(v2, v3);
                __half2 l23 = __floats2half2_rn(v2 - __low2float(h23), v3 - __high2float(h23));
                *reinterpret_cast<__half2*>(Ch + (size_t)r0 * N + col) = h01;
                *reinterpret_cast<__half2*>(Cl + (size_t)r0 * N + col) = l01;
                *reinterpret_cast<__half2*>(Ch + (size_t)(r0 + 8) * N + col) = h23;
                *reinterpret_cast<__half2*>(Cl + (size_t)(r0 + 8) * N + col) = l23;
            }
        }
    }
}

// ---------------- LayerNorm over rows of 768 ----------------
__global__ void __launch_bounds__(256)
ln_kernel(float* __restrict__ out,
          const float* __restrict__ gamma,
          const float* __restrict__ beta) {
    const int row = blockIdx.x;
    float* p = out + (size_t)row * HIDDEN;
    float v[3];
    float s = 0.f, s2 = 0.f;
#pragma unroll
    for (int i = 0; i < 3; i++) {
        v[i] = p[threadIdx.x + i * 256];
        s += v[i];
        s2 += v[i] * v[i];
    }
#pragma unroll
    for (int o = 16; o > 0; o >>= 1) {
        s += __shfl_xor_sync(0xffffffffu, s, o);
        s2 += __shfl_xor_sync(0xffffffffu, s2, o);
    }
    __shared__ float ss[8], ss2[8];
    if ((threadIdx.x & 31) == 0) {
        ss[threadIdx.x >> 5] = s;
        ss2[threadIdx.x >> 5] = s2;
    }
    __syncthreads();
    float st = 0.f, st2 = 0.f;
#pragma unroll
    for (int i = 0; i < 8; i++) { st += ss[i]; st2 += ss2[i]; }
    const float mu = st * (1.0f / HIDDEN);
    const float var = st2 * (1.0f / HIDDEN) - mu * mu;
    const float inv = rsqrtf(var + 1e-5f);
#pragma unroll
    for (int i = 0; i < 3; i++) {
        const int c = threadIdx.x + i * 256;
        p[c] = (v[i] - mu) * inv * __ldg(gamma + c) + __ldg(beta + c);
    }
}

// ---------------- launch ----------------
extern "C" void kernel_launch(void* const* d_in, const int* in_sizes, int n_in,
                              void* d_out, int out_size) {
    const float* x     = (const float*)d_in[0];
    const float* W1    = (const float*)d_in[1];
    const float* b1    = (const float*)d_in[2];
    const float* W2    = (const float*)d_in[3];
    const float* b2    = (const float*)d_in[4];
    const float* Wo    = (const float*)d_in[5];
    const float* bo    = (const float*)d_in[6];
    const float* gamma = (const float*)d_in[7];
    const float* beta  = (const float*)d_in[8];
    float* out = (float*)d_out;
    (void)n_in; (void)out_size;

    const int M = in_sizes[0] / HIDDEN;  // 32768

    void *p_xh, *p_xl, *p_hh, *p_hl, *p_ph, *p_pl, *p_w1, *p_w2, *p_wo;
    cudaGetSymbolAddress(&p_xh, g_xh); cudaGetSymbolAddress(&p_xl, g_xl);
    cudaGetSymbolAddress(&p_hh, g_hh); cudaGetSymbolAddress(&p_hl, g_hl);
    cudaGetSymbolAddress(&p_ph, g_ph); cudaGetSymbolAddress(&p_pl, g_pl);
    cudaGetSymbolAddress(&p_w1, g_w1); cudaGetSymbolAddress(&p_w2, g_w2);
    cudaGetSymbolAddress(&p_wo, g_wo);

    cudaFuncSetAttribute(gemm_h2<0>, cudaFuncAttributeMaxDynamicSharedMemorySize, SMEM_TOTAL);
    cudaFuncSetAttribute(gemm_h2<1>, cudaFuncAttributeMaxDynamicSharedMemorySize, SMEM_TOTAL);
    cudaFuncSetAttribute(gemm_h2<2>, cudaFuncAttributeMaxDynamicSharedMemorySize, SMEM_TOTAL);

    // conversions
    splitx_kernel<<<(M * HIDDEN / 4 + 255) / 256, 256>>>(
        x, (__half*)p_xh, (__half*)p_xl, M * HIDDEN / 4);
    convw_kernel<<<(INNER * HIDDEN / 4 + 255) / 256, 256>>>(W1, (__half*)p_w1, INNER * HIDDEN / 4);
    convw_kernel<<<(HIDDEN * INNER / 4 + 255) / 256, 256>>>(W2, (__half*)p_w2, HIDDEN * INNER / 4);
    convw_kernel<<<(HIDDEN * HIDDEN / 4 + 255) / 256, 256>>>(Wo, (__half*)p_wo, HIDDEN * HIDDEN / 4);

    // GEMM1: h = relu(x @ W1^T + b1) -> fp16 hi/lo
    gemm_h2<0><<<dim3(INNER / BN, M / BM), 256, SMEM_TOTAL>>>(
        (const __half*)p_xh, (const __half*)p_xl, (const __half*)p_w1, b1,
        nullptr, (__half*)p_hh, (__half*)p_hl, INNER, HIDDEN);

    // GEMM2: pred = h @ W2^T + b2 -> fp16 hi/lo
    gemm_h2<1><<<dim3(HIDDEN / BN, M / BM), 256, SMEM_TOTAL>>>(
        (const __half*)p_hh, (const __half*)p_hl, (const __half*)p_w2, b2,
        nullptr, (__half*)p_ph, (__half*)p_pl, HIDDEN, INNER);

    // GEMM3: out_preLN = pred @ Wo^T + bo -> fp32 into d_out
    gemm_h2<2><<<dim3(HIDDEN / BN, M / BM), 256, SMEM_TOTAL>>>(
        (const __half*)p_ph, (const __half*)p_pl, (const __half*)p_wo, bo,
        out, nullptr, nullptr, HIDDEN, HIDDEN);

    // LayerNorm in place
    ln_kernel<<<M, 256>>>(out, gamma, beta);
}

// round 4
// speedup vs baseline: 1.8243x; 1.3946x over previous
#include <cuda_runtime.h>
#include <cuda_fp16.h>
#include <stdint.h>

#define HIDDEN 768
#define INNER  512
#define MAXM   32768

#define BM 128
#define BN 256
#define BK 32
#define ASTR 80                    // bytes per K-row in smem (64 data + 16 pad)
#define STG_A (BM * ASTR)          // 10240
#define STG_B (BN * ASTR)          // 20480
#define STGB (2 * STG_A + STG_B)   // 40960 per stage
#define NSTAGE 4
#define SMEM_TOTAL (NSTAGE * STGB) // 163840

// ---------------- device scratch (allocation-free rule) ----------------
__device__ __half g_xh[(size_t)MAXM * HIDDEN];
__device__ __half g_xl[(size_t)MAXM * HIDDEN];
__device__ __half g_hh[(size_t)MAXM * INNER];
__device__ __half g_hl[(size_t)MAXM * INNER];
__device__ __half g_w1[INNER * HIDDEN];
__device__ __half g_woh[HIDDEN * HIDDEN];
__device__ __half g_wol[HIDDEN * HIDDEN];
__device__ __half g_w2th[INNER * HIDDEN];   // W2^T hi  [512,768]
__device__ __half g_w2tl[INNER * HIDDEN];   // W2^T lo
__device__ __half g_w2o[HIDDEN * INNER];    // fused weight (Wo@W2) fp16 [768,512]
__device__ float  g_bo2[HIDDEN];            // fused bias Wo@b2 + bo

// ---------------- helpers ----------------
__device__ __forceinline__ uint32_t s2u(const void* p) {
    uint32_t a;
    asm("{ .reg .u64 t; cvta.to.shared.u64 t, %1; cvt.u32.u64 %0, t; }" : "=r"(a) : "l"(p));
    return a;
}

__device__ __forceinline__ void ldsm4(uint32_t& d0, uint32_t& d1, uint32_t& d2, uint32_t& d3,
                                      uint32_t addr) {
    asm volatile("ldmatrix.sync.aligned.m8n8.x4.shared.b16 {%0,%1,%2,%3}, [%4];"
                 : "=r"(d0), "=r"(d1), "=r"(d2), "=r"(d3) : "r"(addr));
}

__device__ __forceinline__ void mma_h(float c[4], const uint32_t a[4], const uint32_t b[2]) {
    asm volatile(
        "mma.sync.aligned.m16n8k16.row.col.f32.f16.f16.f32 "
        "{%0,%1,%2,%3}, {%4,%5,%6,%7}, {%8,%9}, {%0,%1,%2,%3};"
        : "+f"(c[0]), "+f"(c[1]), "+f"(c[2]), "+f"(c[3])
        : "r"(a[0]), "r"(a[1]), "r"(a[2]), "r"(a[3]), "r"(b[0]), "r"(b[1]));
}

__device__ __forceinline__ void cpa(uint32_t dst, const void* src) {
    asm volatile("cp.async.cg.shared.global [%0], [%1], 16;" :: "r"(dst), "l"(src));
}
__device__ __forceinline__ void cp_commit() { asm volatile("cp.async.commit_group;"); }
template <int N> __device__ __forceinline__ void cp_wait() {
    asm volatile("cp.async.wait_group %0;" :: "n"(N));
}

// ---------------- conversions ----------------
// fp32 -> fp16 hi/lo pair
__global__ void splitx_kernel(const float* __restrict__ x,
                              __half* __restrict__ hi, __half* __restrict__ lo, int n4) {
    int i = blockIdx.x * blockDim.x + threadIdx.x;
    if (i >= n4) return;
    float4 v = *reinterpret_cast<const float4*>(x + (size_t)i * 4);
    __half2 h01 = __floats2half2_rn(v.x, v.y);
    __half2 h23 = __floats2half2_rn(v.z, v.w);
    __half2 l01 = __floats2half2_rn(v.x - __low2float(h01), v.y - __high2float(h01));
    __half2 l23 = __floats2half2_rn(v.z - __low2float(h23), v.w - __high2float(h23));
    reinterpret_cast<__half2*>(hi)[2 * i]     = h01;
    reinterpret_cast<__half2*>(hi)[2 * i + 1] = h23;
    reinterpret_cast<__half2*>(lo)[2 * i]     = l01;
    reinterpret_cast<__half2*>(lo)[2 * i + 1] = l23;
}

// fp32 -> single fp16
__global__ void convw_kernel(const float* __restrict__ w, __half* __restrict__ o, int n4) {
    int i = blockIdx.x * blockDim.x + threadIdx.x;
    if (i >= n4) return;
    float4 v = *reinterpret_cast<const float4*>(w + (size_t)i * 4);
    reinterpret_cast<__half2*>(o)[2 * i]     = __floats2half2_rn(v.x, v.y);
    reinterpret_cast<__half2*>(o)[2 * i + 1] = __floats2half2_rn(v.z, v.w);
}

// W2[d,i] ([768,512] fp32) -> W2^T hi/lo fp16 [i,d] = [512,768]
__global__ void transp_split_kernel(const float* __restrict__ w2,
                                    __half* __restrict__ th, __half* __restrict__ tl) {
    __shared__ float tile[32][33];
    const int i0 = blockIdx.x * 32, d0 = blockIdx.y * 32;
    const int tx = threadIdx.x, ty = threadIdx.y;  // (32, 8)
#pragma unroll
    for (int r = 0; r < 4; r++) {
        int d = d0 + ty + r * 8;
        tile[ty + r * 8][tx] = w2[(size_t)d * INNER + i0 + tx];
    }
    __syncthreads();
#pragma unroll
    for (int r = 0; r < 4; r++) {
        int i = i0 + ty + r * 8;
        float v = tile[tx][ty + r * 8];
        __half h = __float2half_rn(v);
        th[(size_t)i * HIDDEN + d0 + tx] = h;
        tl[(size_t)i * HIDDEN + d0 + tx] = __float2half_rn(v - __half2float(h));
    }
}

// bo2[e] = bo[e] + sum_d Wo[e,d] * b2[d]   (one warp per e-row)
__global__ void bo2_kernel(const float* __restrict__ Wo, const float* __restrict__ b2,
                           const float* __restrict__ bo, float* __restrict__ bo2) {
    const int warp = (blockIdx.x * blockDim.x + threadIdx.x) >> 5;
    const int lane = threadIdx.x & 31;
    if (warp >= HIDDEN) return;
    float s = 0.f;
    for (int d = lane; d < HIDDEN; d += 32) s += Wo[(size_t)warp * HIDDEN + d] * b2[d];
#pragma unroll
    for (int o = 16; o > 0; o >>= 1) s += __shfl_xor_sync(0xffffffffu, s, o);
    if (lane == 0) bo2[warp] = s + bo[warp];
}

// ---------------- small 3-pass GEMM: W2o[e,i] = Wo[e,:] . W2T[i,:] -> fp16 ----------------
// A = Wo hi/lo [768,768], B = W2T hi/lo [512,768]. C = fp16 [768,512].
// Double-buffered, BM=128 BN=256 BK=32. Stage: Ah,Al(10240 ea) Bh,Bl(20480 ea) = 61440.
#define WSTG 61440
#define WSMEM (2 * WSTG)
__global__ void __launch_bounds__(256, 1)
gemm_w2o(const __half* __restrict__ Ah, const __half* __restrict__ Al,
         const __half* __restrict__ Bh, const __half* __restrict__ Bl,
         __half* __restrict__ C, int N, int K) {
    extern __shared__ __align__(128) char smem[];
    const uint32_t sb = s2u(smem);
    const int tid = threadIdx.x, lane = tid & 31, warp = tid >> 5;
    const int m0 = blockIdx.y * BM, n0 = blockIdx.x * BN;
    const int wm = (warp >> 2) * 64, wn = (warp & 3) * 64;
    const __half* Agh = Ah + (size_t)m0 * K;
    const __half* Agl = Al + (size_t)m0 * K;
    const __half* Bgh = Bh + (size_t)n0 * K;
    const __half* Bgl = Bl + (size_t)n0 * K;
    const int T = K / BK;

    float acc[4][8][4];
#pragma unroll
    for (int i = 0; i < 4; i++)
#pragma unroll
        for (int j = 0; j < 8; j++)
#pragma unroll
            for (int r = 0; r < 4; r++) acc[i][j][r] = 0.f;

    auto load_stage = [&](int s, int t) {
        const uint32_t so = sb + s * WSTG;
        const int k0 = t * BK;
#pragma unroll
        for (int it = 0; it < 2; it++) {
            int idx = tid + it * 256;
            int r = idx >> 2, c = idx & 3;
            cpa(so + r * ASTR + c * 16, (const char*)(Agh + (size_t)r * K + k0) + c * 16);
            cpa(so + STG_A + r * ASTR + c * 16, (const char*)(Agl + (size_t)r * K + k0) + c * 16);
        }
#pragma unroll
        for (int it = 0; it < 4; it++) {
            int idx = tid + it * 256;
            int r = idx >> 2, c = idx & 3;
            cpa(so + 2 * STG_A + r * ASTR + c * 16, (const char*)(Bgh + (size_t)r * K + k0) + c * 16);
            cpa(so + 2 * STG_A + STG_B + r * ASTR + c * 16,
                (const char*)(Bgl + (size_t)r * K + k0) + c * 16);
        }
        cp_commit();
    };

    const int a_row = wm + ((lane >> 3) & 1) * 8 + (lane & 7);
    const int a_kh  = ((lane >> 4) & 1) * 8;
    const int b_row = wn + ((lane >> 4) & 1) * 8 + (lane & 7);
    const int b_kh  = ((lane >> 3) & 1) * 8;

    load_stage(0, 0);
    for (int t = 0; t < T; t++) {
        if (t + 1 < T) load_stage((t + 1) & 1, t + 1);
        if (t + 1 < T) cp_wait<1>(); else cp_wait<0>();
        __syncthreads();
        const uint32_t so = sb + (t & 1) * WSTG;
#pragma unroll
        for (int kk = 0; kk < 2; kk++) {
            const int kc2 = (kk * 16 + a_kh) * 2;
            const int kb2 = (kk * 16 + b_kh) * 2;
            uint32_t ah[4][4], al[4][4], b[8][2];
#pragma unroll
            for (int j2 = 0; j2 < 4; j2++)
                ldsm4(b[2 * j2][0], b[2 * j2][1], b[2 * j2 + 1][0], b[2 * j2 + 1][1],
                      so + 2 * STG_A + (b_row + j2 * 16) * ASTR + kb2);
#pragma unroll
            for (int i = 0; i < 4; i++)
                ldsm4(ah[i][0], ah[i][1], ah[i][2], ah[i][3],
                      so + (a_row + i * 16) * ASTR + kc2);
#pragma unroll
            for (int i = 0; i < 4; i++)
#pragma unroll
                for (int j = 0; j < 8; j++) mma_h(acc[i][j], ah[i], b[j]);
#pragma unroll
            for (int i = 0; i < 4; i++)
                ldsm4(al[i][0], al[i][1], al[i][2], al[i][3],
                      so + STG_A + (a_row + i * 16) * ASTR + kc2);
#pragma unroll
            for (int i = 0; i < 4; i++)
#pragma unroll
                for (int j = 0; j < 8; j++) mma_h(acc[i][j], al[i], b[j]);
#pragma unroll
            for (int j2 = 0; j2 < 4; j2++)
                ldsm4(b[2 * j2][0], b[2 * j2][1], b[2 * j2 + 1][0], b[2 * j2 + 1][1],
                      so + 2 * STG_A + STG_B + (b_row + j2 * 16) * ASTR + kb2);
#pragma unroll
            for (int i = 0; i < 4; i++)
#pragma unroll
                for (int j = 0; j < 8; j++) mma_h(acc[i][j], ah[i], b[j]);
        }
        __syncthreads();
    }

    const int erow = lane >> 2, ecol = (lane & 3) * 2;
#pragma unroll
    for (int i = 0; i < 4; i++) {
        const int r0 = m0 + wm + i * 16 + erow;
#pragma unroll
        for (int j = 0; j < 8; j++) {
            const int col = n0 + wn + j * 8 + ecol;
            *reinterpret_cast<__half2*>(C + (size_t)r0 * N + col) =
                __floats2half2_rn(acc[i][j][0], acc[i][j][1]);
            *reinterpret_cast<__half2*>(C + (size_t)(r0 + 8) * N + col) =
                __floats2half2_rn(acc[i][j][2], acc[i][j][3]);
        }
    }
}

// ---------------- main GEMM: C[M,N] = (Ah+Al)[M,K] @ B[N,K]^T + bias ----------------
// CTA 128x256, 8 warps (2x4 of 64x64), BK=32, 4-stage cp.async.
// EPI: 0 = relu + fp16 hi/lo out, 2 = fp32 out
template <int EPI>
__global__ void __launch_bounds__(256, 1)
gemm_h2(const __half* __restrict__ Ah, const __half* __restrict__ Al,
        const __half* __restrict__ B, const float* __restrict__ bias,
        float* __restrict__ Co, __half* __restrict__ Ch, __half* __restrict__ Cl,
        int N, int K) {
    extern __shared__ __align__(128) char smem[];
    const uint32_t sb = s2u(smem);
    const int tid = threadIdx.x, lane = tid & 31, warp = tid >> 5;
    const int m0 = blockIdx.y * BM, n0 = blockIdx.x * BN;
    const int wm = (warp >> 2) * 64;
    const int wn = (warp & 3) * 64;

    const __half* Agh = Ah + (size_t)m0 * K;
    const __half* Agl = Al + (size_t)m0 * K;
    const __half* Bg  = B + (size_t)n0 * K;
    const int T = K / BK;

    float acc[4][8][4];
#pragma unroll
    for (int i = 0; i < 4; i++)
#pragma unroll
        for (int j = 0; j < 8; j++)
#pragma unroll
            for (int r = 0; r < 4; r++) acc[i][j][r] = 0.f;

    auto load_stage = [&](int s, int t) {
        const uint32_t so = sb + s * STGB;
        const int k0 = t * BK;
#pragma unroll
        for (int it = 0; it < 2; it++) {
            int idx = tid + it * 256;
            int r = idx >> 2, c = idx & 3;
            cpa(so + r * ASTR + c * 16, (const char*)(Agh + (size_t)r * K + k0) + c * 16);
            cpa(so + STG_A + r * ASTR + c * 16, (const char*)(Agl + (size_t)r * K + k0) + c * 16);
        }
#pragma unroll
        for (int it = 0; it < 4; it++) {
            int idx = tid + it * 256;
            int r = idx >> 2, c = idx & 3;
            cpa(so + 2 * STG_A + r * ASTR + c * 16, (const char*)(Bg + (size_t)r * K + k0) + c * 16);
        }
        cp_commit();
    };

    load_stage(0, 0);
    load_stage(1, 1);
    load_stage(2, 2);

    const int a_row = wm + ((lane >> 3) & 1) * 8 + (lane & 7);
    const int a_kh  = ((lane >> 4) & 1) * 8;
    const int b_row = wn + ((lane >> 4) & 1) * 8 + (lane & 7);
    const int b_kh  = ((lane >> 3) & 1) * 8;

    for (int t = 0; t < T; t++) {
        if (t <= T - 3) cp_wait<2>();
        else if (t == T - 2) cp_wait<1>();
        else cp_wait<0>();
        __syncthreads();
        if (t + 3 < T) load_stage((t + 3) & 3, t + 3);

        const uint32_t so = sb + (t & 3) * STGB;
#pragma unroll
        for (int kk = 0; kk < 2; kk++) {
            const int kc = kk * 16;
            uint32_t b[8][2];
#pragma unroll
            for (int j2 = 0; j2 < 4; j2++)
                ldsm4(b[2 * j2][0], b[2 * j2][1], b[2 * j2 + 1][0], b[2 * j2 + 1][1],
                      so + 2 * STG_A + (b_row + j2 * 16) * ASTR + (kc + b_kh) * 2);
            uint32_t a[4][4];
#pragma unroll
            for (int i = 0; i < 4; i++)
                ldsm4(a[i][0], a[i][1], a[i][2], a[i][3],
                      so + (a_row + i * 16) * ASTR + (kc + a_kh) * 2);
#pragma unroll
            for (int i = 0; i < 4; i++)
#pragma unroll
                for (int j = 0; j < 8; j++) mma_h(acc[i][j], a[i], b[j]);
#pragma unroll
            for (int i = 0; i < 4; i++)
                ldsm4(a[i][0], a[i][1], a[i][2], a[i][3],
                      so + STG_A + (a_row + i * 16) * ASTR + (kc + a_kh) * 2);
#pragma unroll
            for (int i = 0; i < 4; i++)
#pragma unroll
                for (int j = 0; j < 8; j++) mma_h(acc[i][j], a[i], b[j]);
        }
    }

    const int erow = lane >> 2;
    const int ecol = (lane & 3) * 2;
#pragma unroll
    for (int i = 0; i < 4; i++) {
        const int r0 = m0 + wm + i * 16 + erow;
#pragma unroll
        for (int j = 0; j < 8; j++) {
            const int col = n0 + wn + j * 8 + ecol;
            const float bv0 = __ldg(bias + col);
            const float bv1 = __ldg(bias + col + 1);
            float v0 = acc[i][j][0] + bv0;
            float v1 = acc[i][j][1] + bv1;
            float v2 = acc[i][j][2] + bv0;
            float v3 = acc[i][j][3] + bv1;
            if (EPI == 0) {
                v0 = fmaxf(v0, 0.f); v1 = fmaxf(v1, 0.f);
                v2 = fmaxf(v2, 0.f); v3 = fmaxf(v3, 0.f);
            }
            if (EPI == 2) {
                *reinterpret_cast<float2*>(Co + (size_t)r0 * N + col) = make_float2(v0, v1);
                *reinterpret_cast<float2*>(Co + (size_t)(r0 + 8) * N + col) = make_float2(v2, v3);
            } else {
                __half2 h01 = __floats2half2_rn(v0, v1);
                __half2 l01 = __floats2half2_rn(v0 - __low2float(h01), v1 - __high2float(h01));
                __half2 h23 = __floats2half2_rn(v2, v3);
                __half2 l23 = __floats2half2_rn(v2 - __low2float(h23), v3 - __high2float(h23));
                *reinterpret_cast<__half2*>(Ch + (size_t)r0 * N + col) = h01;
                *reinterpret_cast<__half2*>(Cl + (size_t)r0 * N + col) = l01;
                *reinterpret_cast<__half2*>(Ch + (size_t)(r0 + 8) * N + col) = h23;
                *reinterpret_cast<__half2*>(Cl + (size_t)(r0 + 8) * N + col) = l23;
            }
        }
    }
}

// ---------------- LayerNorm over rows of 768 ----------------
__global__ void __launch_bounds__(256)
ln_kernel(float* __restrict__ out,
          const float* __restrict__ gamma,
          const float* __restrict__ beta) {
    const int row = blockIdx.x;
    float* p = out + (size_t)row * HIDDEN;
    float v[3];
    float s = 0.f, s2 = 0.f;
#pragma unroll
    for (int i = 0; i < 3; i++) {
        v[i] = p[threadIdx.x + i * 256];
        s += v[i];
        s2 += v[i] * v[i];
    }
#pragma unroll
    for (int o = 16; o > 0; o >>= 1) {
        s += __shfl_xor_sync(0xffffffffu, s, o);
        s2 += __shfl_xor_sync(0xffffffffu, s2, o);
    }
    __shared__ float ss[8], ss2[8];
    if ((threadIdx.x & 31) == 0) {
        ss[threadIdx.x >> 5] = s;
        ss2[threadIdx.x >> 5] = s2;
    }
    __syncthreads();
    float st = 0.f, st2 = 0.f;
#pragma unroll
    for (int i = 0; i < 8; i++) { st += ss[i]; st2 += ss2[i]; }
    const float mu = st * (1.0f / HIDDEN);
    const float var = st2 * (1.0f / HIDDEN) - mu * mu;
    const float inv = rsqrtf(var + 1e-5f);
#pragma unroll
    for (int i = 0; i < 3; i++) {
        const int c = threadIdx.x + i * 256;
        p[c] = (v[i] - mu) * inv * __ldg(gamma + c) + __ldg(beta + c);
    }
}

// ---------------- launch ----------------
extern "C" void kernel_launch(void* const* d_in, const int* in_sizes, int n_in,
                              void* d_out, int out_size) {
    const float* x     = (const float*)d_in[0];
    const float* W1    = (const float*)d_in[1];
    const float* b1    = (const float*)d_in[2];
    const float* W2    = (const float*)d_in[3];
    const float* b2    = (const float*)d_in[4];
    const float* Wo    = (const float*)d_in[5];
    const float* bo    = (const float*)d_in[6];
    const float* gamma = (const float*)d_in[7];
    const float* beta  = (const float*)d_in[8];
    float* out = (float*)d_out;
    (void)n_in; (void)out_size;

    const int M = in_sizes[0] / HIDDEN;  // 32768

    void *p_xh, *p_xl, *p_hh, *p_hl, *p_w1, *p_woh, *p_wol, *p_w2th, *p_w2tl, *p_w2o, *p_bo2;
    cudaGetSymbolAddress(&p_xh, g_xh);     cudaGetSymbolAddress(&p_xl, g_xl);
    cudaGetSymbolAddress(&p_hh, g_hh);     cudaGetSymbolAddress(&p_hl, g_hl);
    cudaGetSymbolAddress(&p_w1, g_w1);     cudaGetSymbolAddress(&p_woh, g_woh);
    cudaGetSymbolAddress(&p_wol, g_wol);   cudaGetSymbolAddress(&p_w2th, g_w2th);
    cudaGetSymbolAddress(&p_w2tl, g_w2tl); cudaGetSymbolAddress(&p_w2o, g_w2o);
    cudaGetSymbolAddress(&p_bo2, g_bo2);

    cudaFuncSetAttribute(gemm_h2<0>, cudaFuncAttributeMaxDynamicSharedMemorySize, SMEM_TOTAL);
    cudaFuncSetAttribute(gemm_h2<2>, cudaFuncAttributeMaxDynamicSharedMemorySize, SMEM_TOTAL);
    cudaFuncSetAttribute(gemm_w2o, cudaFuncAttributeMaxDynamicSharedMemorySize, WSMEM);

    // [0] x -> fp16 hi/lo
    splitx_kernel<<<(M * HIDDEN / 4 + 255) / 256, 256>>>(
        x, (__half*)p_xh, (__half*)p_xl, M * HIDDEN / 4);
    // [1] W1 -> fp16
    convw_kernel<<<(INNER * HIDDEN / 4 + 255) / 256, 256>>>(W1, (__half*)p_w1, INNER * HIDDEN / 4);
    // [2] Wo -> fp16 hi/lo
    splitx_kernel<<<(HIDDEN * HIDDEN / 4 + 255) / 256, 256>>>(
        Wo, (__half*)p_woh, (__half*)p_wol, HIDDEN * HIDDEN / 4);
    // [3] W2 -> W2^T hi/lo
    transp_split_kernel<<<dim3(INNER / 32, HIDDEN / 32), dim3(32, 8)>>>(
        W2, (__half*)p_w2th, (__half*)p_w2tl);
    // [4] bo2 = Wo@b2 + bo
    bo2_kernel<<<(HIDDEN * 32 + 255) / 256, 256>>>(Wo, b2, bo, (float*)p_bo2);
    // [5] GEMM1: h = relu(x @ W1^T + b1) -> fp16 hi/lo   (profiled launch)
    gemm_h2<0><<<dim3(INNER / BN, M / BM), 256, SMEM_TOTAL>>>(
        (const __half*)p_xh, (const __half*)p_xl, (const __half*)p_w1, b1,
        nullptr, (__half*)p_hh, (__half*)p_hl, INNER, HIDDEN);
    // [6] W2o = Wo @ W2 (3-pass accurate) -> fp16
    gemm_w2o<<<dim3(INNER / BN, HIDDEN / BM), 256, WSMEM>>>(
        (const __half*)p_woh, (const __half*)p_wol,
        (const __half*)p_w2th, (const __half*)p_w2tl,
        (__half*)p_w2o, INNER, HIDDEN);
    // [7] out = h @ W2o^T + bo2 -> fp32
    gemm_h2<2><<<dim3(HIDDEN / BN, M / BM), 256, SMEM_TOTAL>>>(
        (const __half*)p_hh, (const __half*)p_hl, (const __half*)p_w2o, (const float*)p_bo2,
        out, nullptr, nullptr, HIDDEN, INNER);
    // [8] LayerNorm in place
    ln_kernel<<<M, 256>>>(out, gamma, beta);
}

// round 6
// speedup vs baseline: 2.5942x; 1.4220x over previous
#include <cuda_runtime.h>
#include <cuda_fp16.h>
#include <stdint.h>

#define HIDDEN 768
#define INNER  512
#define MAXM   32768

// ---- main GEMM tiles: CTA 128x256, BK=64, 3-stage cp.async ----
#define BM 128
#define BN 256
#define BK 64
#define ASTR 144                    // bytes per K-row (128 data + 16 pad)
#define STG_A (BM * ASTR)           // 18432
#define STG_B (BN * ASTR)           // 36864
#define STGB (STG_A + STG_B)        // 55296
#define SMEM_TOTAL (3 * STGB)       // 165888

// ---- w2o GEMM tiles (BK=32 legacy layout) ----
#define WASTR 80
#define WSTG_A (128 * WASTR)        // 10240
#define WSTG_B (256 * WASTR)        // 20480
#define WSTG (2 * WSTG_A + 2 * WSTG_B)  // 61440
#define WSMEM (2 * WSTG)

// ---------------- device scratch (allocation-free rule) ----------------
__device__ __half g_x16[(size_t)MAXM * HIDDEN];
__device__ __half g_h16[(size_t)MAXM * INNER];
__device__ __half g_w1[INNER * HIDDEN];
__device__ __half g_woh[HIDDEN * HIDDEN];
__device__ __half g_wol[HIDDEN * HIDDEN];
__device__ __half g_w2th[INNER * HIDDEN];
__device__ __half g_w2tl[INNER * HIDDEN];
__device__ __half g_w2o[HIDDEN * INNER];    // fused weight (Wo@W2) fp16 [768,512]
__device__ float  g_bo2[HIDDEN];            // fused bias Wo@b2 + bo

// ---------------- helpers ----------------
__device__ __forceinline__ uint32_t s2u(const void* p) {
    uint32_t a;
    asm("{ .reg .u64 t; cvta.to.shared.u64 t, %1; cvt.u32.u64 %0, t; }" : "=r"(a) : "l"(p));
    return a;
}

__device__ __forceinline__ void ldsm4(uint32_t& d0, uint32_t& d1, uint32_t& d2, uint32_t& d3,
                                      uint32_t addr) {
    asm volatile("ldmatrix.sync.aligned.m8n8.x4.shared.b16 {%0,%1,%2,%3}, [%4];"
                 : "=r"(d0), "=r"(d1), "=r"(d2), "=r"(d3) : "r"(addr));
}

__device__ __forceinline__ void mma_h(float c[4], const uint32_t a[4], const uint32_t b[2]) {
    asm volatile(
        "mma.sync.aligned.m16n8k16.row.col.f32.f16.f16.f32 "
        "{%0,%1,%2,%3}, {%4,%5,%6,%7}, {%8,%9}, {%0,%1,%2,%3};"
        : "+f"(c[0]), "+f"(c[1]), "+f"(c[2]), "+f"(c[3])
        : "r"(a[0]), "r"(a[1]), "r"(a[2]), "r"(a[3]), "r"(b[0]), "r"(b[1]));
}

__device__ __forceinline__ void cpa(uint32_t dst, const void* src) {
    asm volatile("cp.async.cg.shared.global [%0], [%1], 16;" :: "r"(dst), "l"(src));
}
__device__ __forceinline__ void cp_commit() { asm volatile("cp.async.commit_group;"); }
template <int N> __device__ __forceinline__ void cp_wait() {
    asm volatile("cp.async.wait_group %0;" :: "n"(N));
}

// ---------------- conversions ----------------
// fp32 -> single fp16 (used for x and W1)
__global__ void convw_kernel(const float* __restrict__ w, __half* __restrict__ o, int n4) {
    int i = blockIdx.x * blockDim.x + threadIdx.x;
    if (i >= n4) return;
    float4 v = *reinterpret_cast<const float4*>(w + (size_t)i * 4);
    reinterpret_cast<__half2*>(o)[2 * i]     = __floats2half2_rn(v.x, v.y);
    reinterpret_cast<__half2*>(o)[2 * i + 1] = __floats2half2_rn(v.z, v.w);
}

// fp32 -> fp16 hi/lo pair (Wo, for accurate W2o precompute)
__global__ void splitx_kernel(const float* __restrict__ x,
                              __half* __restrict__ hi, __half* __restrict__ lo, int n4) {
    int i = blockIdx.x * blockDim.x + threadIdx.x;
    if (i >= n4) return;
    float4 v = *reinterpret_cast<const float4*>(x + (size_t)i * 4);
    __half2 h01 = __floats2half2_rn(v.x, v.y);
    __half2 h23 = __floats2half2_rn(v.z, v.w);
    __half2 l01 = __floats2half2_rn(v.x - __low2float(h01), v.y - __high2float(h01));
    __half2 l23 = __floats2half2_rn(v.z - __low2float(h23), v.w - __high2float(h23));
    reinterpret_cast<__half2*>(hi)[2 * i]     = h01;
    reinterpret_cast<__half2*>(hi)[2 * i + 1] = h23;
    reinterpret_cast<__half2*>(lo)[2 * i]     = l01;
    reinterpret_cast<__half2*>(lo)[2 * i + 1] = l23;
}

// W2[d,i] ([768,512] fp32) -> W2^T hi/lo fp16 [i,d] = [512,768]
__global__ void transp_split_kernel(const float* __restrict__ w2,
                                    __half* __restrict__ th, __half* __restrict__ tl) {
    __shared__ float tile[32][33];
    const int i0 = blockIdx.x * 32, d0 = blockIdx.y * 32;
    const int tx = threadIdx.x, ty = threadIdx.y;  // (32, 8)
#pragma unroll
    for (int r = 0; r < 4; r++) {
        int d = d0 + ty + r * 8;
        tile[ty + r * 8][tx] = w2[(size_t)d * INNER + i0 + tx];
    }
    __syncthreads();
#pragma unroll
    for (int r = 0; r < 4; r++) {
        int i = i0 + ty + r * 8;
        float v = tile[tx][ty + r * 8];
        __half h = __float2half_rn(v);
        th[(size_t)i * HIDDEN + d0 + tx] = h;
        tl[(size_t)i * HIDDEN + d0 + tx] = __float2half_rn(v - __half2float(h));
    }
}

// bo2[e] = bo[e] + sum_d Wo[e,d] * b2[d]
__global__ void bo2_kernel(const float* __restrict__ Wo, const float* __restrict__ b2,
                           const float* __restrict__ bo, float* __restrict__ bo2) {
    const int warp = (blockIdx.x * blockDim.x + threadIdx.x) >> 5;
    const int lane = threadIdx.x & 31;
    if (warp >= HIDDEN) return;
    float s = 0.f;
    for (int d = lane; d < HIDDEN; d += 32) s += Wo[(size_t)warp * HIDDEN + d] * b2[d];
#pragma unroll
    for (int o = 16; o > 0; o >>= 1) s += __shfl_xor_sync(0xffffffffu, s, o);
    if (lane == 0) bo2[warp] = s + bo[warp];
}

// ---------------- accurate 3-pass GEMM: W2o = Wo @ W2 -> fp16 ----------------
__global__ void __launch_bounds__(256, 1)
gemm_w2o(const __half* __restrict__ Ah, const __half* __restrict__ Al,
         const __half* __restrict__ Bh, const __half* __restrict__ Bl,
         __half* __restrict__ C, int N, int K) {
    extern __shared__ __align__(128) char smem[];
    const uint32_t sb = s2u(smem);
    const int tid = threadIdx.x, lane = tid & 31, warp = tid >> 5;
    const int m0 = blockIdx.y * BM, n0 = blockIdx.x * BN;
    const int wm = (warp >> 2) * 64, wn = (warp & 3) * 64;
    const __half* Agh = Ah + (size_t)m0 * K;
    const __half* Agl = Al + (size_t)m0 * K;
    const __half* Bgh = Bh + (size_t)n0 * K;
    const __half* Bgl = Bl + (size_t)n0 * K;
    const int T = K / 32;

    float acc[4][8][4];
#pragma unroll
    for (int i = 0; i < 4; i++)
#pragma unroll
        for (int j = 0; j < 8; j++)
#pragma unroll
            for (int r = 0; r < 4; r++) acc[i][j][r] = 0.f;

    auto load_stage = [&](int s, int t) {
        const uint32_t so = sb + s * WSTG;
        const int k0 = t * 32;
#pragma unroll
        for (int it = 0; it < 2; it++) {
            int idx = tid + it * 256;
            int r = idx >> 2, c = idx & 3;
            cpa(so + r * WASTR + c * 16, (const char*)(Agh + (size_t)r * K + k0) + c * 16);
            cpa(so + WSTG_A + r * WASTR + c * 16, (const char*)(Agl + (size_t)r * K + k0) + c * 16);
        }
#pragma unroll
        for (int it = 0; it < 4; it++) {
            int idx = tid + it * 256;
            int r = idx >> 2, c = idx & 3;
            cpa(so + 2 * WSTG_A + r * WASTR + c * 16,
                (const char*)(Bgh + (size_t)r * K + k0) + c * 16);
            cpa(so + 2 * WSTG_A + WSTG_B + r * WASTR + c * 16,
                (const char*)(Bgl + (size_t)r * K + k0) + c * 16);
        }
        cp_commit();
    };

    const int a_row = wm + ((lane >> 3) & 1) * 8 + (lane & 7);
    const int a_kh  = ((lane >> 4) & 1) * 8;
    const int b_row = wn + ((lane >> 4) & 1) * 8 + (lane & 7);
    const int b_kh  = ((lane >> 3) & 1) * 8;

    load_stage(0, 0);
    for (int t = 0; t < T; t++) {
        if (t + 1 < T) load_stage((t + 1) & 1, t + 1);
        if (t + 1 < T) cp_wait<1>(); else cp_wait<0>();
        __syncthreads();
        const uint32_t so = sb + (t & 1) * WSTG;
#pragma unroll
        for (int kk = 0; kk < 2; kk++) {
            const int kc2 = (kk * 16 + a_kh) * 2;
            const int kb2 = (kk * 16 + b_kh) * 2;
            uint32_t ah[4][4], al[4][4], b[8][2];
#pragma unroll
            for (int j2 = 0; j2 < 4; j2++)
                ldsm4(b[2 * j2][0], b[2 * j2][1], b[2 * j2 + 1][0], b[2 * j2 + 1][1],
                      so + 2 * WSTG_A + (b_row + j2 * 16) * WASTR + kb2);
#pragma unroll
            for (int i = 0; i < 4; i++)
                ldsm4(ah[i][0], ah[i][1], ah[i][2], ah[i][3],
                      so + (a_row + i * 16) * WASTR + kc2);
#pragma unroll
            for (int i = 0; i < 4; i++)
#pragma unroll
                for (int j = 0; j < 8; j++) mma_h(acc[i][j], ah[i], b[j]);
#pragma unroll
            for (int i = 0; i < 4; i++)
                ldsm4(al[i][0], al[i][1], al[i][2], al[i][3],
                      so + WSTG_A + (a_row + i * 16) * WASTR + kc2);
#pragma unroll
            for (int i = 0; i < 4; i++)
#pragma unroll
                for (int j = 0; j < 8; j++) mma_h(acc[i][j], al[i], b[j]);
#pragma unroll
            for (int j2 = 0; j2 < 4; j2++)
                ldsm4(b[2 * j2][0], b[2 * j2][1], b[2 * j2 + 1][0], b[2 * j2 + 1][1],
                      so + 2 * WSTG_A + WSTG_B + (b_row + j2 * 16) * WASTR + kb2);
#pragma unroll
            for (int i = 0; i < 4; i++)
#pragma unroll
                for (int j = 0; j < 8; j++) mma_h(acc[i][j], ah[i], b[j]);
        }
        __syncthreads();
    }

    const int erow = lane >> 2, ecol = (lane & 3) * 2;
#pragma unroll
    for (int i = 0; i < 4; i++) {
        const int r0 = m0 + wm + i * 16 + erow;
#pragma unroll
        for (int j = 0; j < 8; j++) {
            const int col = n0 + wn + j * 8 + ecol;
            *reinterpret_cast<__half2*>(C + (size_t)r0 * N + col) =
                __floats2half2_rn(acc[i][j][0], acc[i][j][1]);
            *reinterpret_cast<__half2*>(C + (size_t)(r0 + 8) * N + col) =
                __floats2half2_rn(acc[i][j][2], acc[i][j][3]);
        }
    }
}

// ---------------- main single-pass GEMM: C[M,N] = A[M,K] @ B[N,K]^T + bias ----------------
// CTA 128x256, 8 warps (2x4 of 64x64), BK=64, 3-stage cp.async.
// EPI: 0 = relu + fp16 out, 2 = fp32 out
template <int EPI>
__global__ void __launch_bounds__(256, 1)
gemm_h1(const __half* __restrict__ A, const __half* __restrict__ B,
        const float* __restrict__ bias,
        float* __restrict__ Co, __half* __restrict__ Ch, int N, int K) {
    extern __shared__ __align__(128) char smem[];
    const uint32_t sb = s2u(smem);
    const int tid = threadIdx.x, lane = tid & 31, warp = tid >> 5;
    const int m0 = blockIdx.y * BM, n0 = blockIdx.x * BN;
    const int wm = (warp >> 2) * 64;
    const int wn = (warp & 3) * 64;

    const __half* Ag = A + (size_t)m0 * K;
    const __half* Bg = B + (size_t)n0 * K;
    const int T = K / BK;

    float acc[4][8][4];
#pragma unroll
    for (int i = 0; i < 4; i++)
#pragma unroll
        for (int j = 0; j < 8; j++)
#pragma unroll
            for (int r = 0; r < 4; r++) acc[i][j][r] = 0.f;

    auto load_stage = [&](int s, int t) {
        const uint32_t so = sb + s * STGB;
        const int k0 = t * BK;
#pragma unroll
        for (int it = 0; it < 4; it++) {     // A: 128 rows x 8 chunks
            int idx = tid + it * 256;
            int r = idx >> 3, c = idx & 7;
            cpa(so + r * ASTR + c * 16, (const char*)(Ag + (size_t)r * K + k0) + c * 16);
        }
#pragma unroll
        for (int it = 0; it < 8; it++) {     // B: 256 rows x 8 chunks
            int idx = tid + it * 256;
            int r = idx >> 3, c = idx & 7;
            cpa(so + STG_A + r * ASTR + c * 16, (const char*)(Bg + (size_t)r * K + k0) + c * 16);
        }
        cp_commit();
    };

    load_stage(0, 0);
    load_stage(1, 1);

    const int a_row = wm + ((lane >> 3) & 1) * 8 + (lane & 7);
    const int a_kh  = ((lane >> 4) & 1) * 8;
    const int b_row = wn + ((lane >> 4) & 1) * 8 + (lane & 7);
    const int b_kh  = ((lane >> 3) & 1) * 8;

    for (int t = 0; t < T; t++) {
        if (t + 1 < T) cp_wait<1>(); else cp_wait<0>();
        __syncthreads();
        if (t + 2 < T) load_stage((t + 2) % 3, t + 2);

        const uint32_t so = sb + (t % 3) * STGB;
#pragma unroll
        for (int kk = 0; kk < 4; kk++) {
            const int ka2 = (kk * 16 + a_kh) * 2;
            const int kb2 = (kk * 16 + b_kh) * 2;
            uint32_t b[8][2];
#pragma unroll
            for (int j2 = 0; j2 < 4; j2++)
                ldsm4(b[2 * j2][0], b[2 * j2][1], b[2 * j2 + 1][0], b[2 * j2 + 1][1],
                      so + STG_A + (b_row + j2 * 16) * ASTR + kb2);
            uint32_t a[4][4];
#pragma unroll
            for (int i = 0; i < 4; i++)
                ldsm4(a[i][0], a[i][1], a[i][2], a[i][3],
                      so + (a_row + i * 16) * ASTR + ka2);
#pragma unroll
            for (int i = 0; i < 4; i++)
#pragma unroll
                for (int j = 0; j < 8; j++) mma_h(acc[i][j], a[i], b[j]);
        }
    }

    const int erow = lane >> 2;
    const int ecol = (lane & 3) * 2;
#pragma unroll
    for (int i = 0; i < 4; i++) {
        const int r0 = m0 + wm + i * 16 + erow;
#pragma unroll
        for (int j = 0; j < 8; j++) {
            const int col = n0 + wn + j * 8 + ecol;
            const float bv0 = __ldg(bias + col);
            const float bv1 = __ldg(bias + col + 1);
            float v0 = acc[i][j][0] + bv0;
            float v1 = acc[i][j][1] + bv1;
            float v2 = acc[i][j][2] + bv0;
            float v3 = acc[i][j][3] + bv1;
            if (EPI == 0) {
                v0 = fmaxf(v0, 0.f); v1 = fmaxf(v1, 0.f);
                v2 = fmaxf(v2, 0.f); v3 = fmaxf(v3, 0.f);
                *reinterpret_cast<__half2*>(Ch + (size_t)r0 * N + col) = __floats2half2_rn(v0, v1);
                *reinterpret_cast<__half2*>(Ch + (size_t)(r0 + 8) * N + col) = __floats2half2_rn(v2, v3);
            } else {
                *reinterpret_cast<float2*>(Co + (size_t)r0 * N + col) = make_float2(v0, v1);
                *reinterpret_cast<float2*>(Co + (size_t)(r0 + 8) * N + col) = make_float2(v2, v3);
            }
        }
    }
}

// ---------------- LayerNorm over rows of 768 ----------------
__global__ void __launch_bounds__(256)
ln_kernel(float* __restrict__ out,
          const float* __restrict__ gamma,
          const float* __restrict__ beta) {
    const int row = blockIdx.x;
    float* p = out + (size_t)row * HIDDEN;
    float v[3];
    float s = 0.f, s2 = 0.f;
#pragma unroll
    for (int i = 0; i < 3; i++) {
        v[i] = p[threadIdx.x + i * 256];
        s += v[i];
        s2 += v[i] * v[i];
    }
#pragma unroll
    for (int o = 16; o > 0; o >>= 1) {
        s += __shfl_xor_sync(0xffffffffu, s, o);
        s2 += __shfl_xor_sync(0xffffffffu, s2, o);
    }
    __shared__ float ss[8], ss2[8];
    if ((threadIdx.x & 31) == 0) {
        ss[threadIdx.x >> 5] = s;
        ss2[threadIdx.x >> 5] = s2;
    }
    __syncthreads();
    float st = 0.f, st2 = 0.f;
#pragma unroll
    for (int i = 0; i < 8; i++) { st += ss[i]; st2 += ss2[i]; }
    const float mu = st * (1.0f / HIDDEN);
    const float var = st2 * (1.0f / HIDDEN) - mu * mu;
    const float inv = rsqrtf(var + 1e-5f);
#pragma unroll
    for (int i = 0; i < 3; i++) {
        const int c = threadIdx.x + i * 256;
        p[c] = (v[i] - mu) * inv * __ldg(gamma + c) + __ldg(beta + c);
    }
}

// ---------------- launch ----------------
extern "C" void kernel_launch(void* const* d_in, const int* in_sizes, int n_in,
                              void* d_out, int out_size) {
    const float* x     = (const float*)d_in[0];
    const float* W1    = (const float*)d_in[1];
    const float* b1    = (const float*)d_in[2];
    const float* W2    = (const float*)d_in[3];
    const float* b2    = (const float*)d_in[4];
    const float* Wo    = (const float*)d_in[5];
    const float* bo    = (const float*)d_in[6];
    const float* gamma = (const float*)d_in[7];
    const float* beta  = (const float*)d_in[8];
    float* out = (float*)d_out;
    (void)n_in; (void)out_size;

    const int M = in_sizes[0] / HIDDEN;  // 32768

    void *p_x16, *p_h16, *p_w1, *p_woh, *p_wol, *p_w2th, *p_w2tl, *p_w2o, *p_bo2;
    cudaGetSymbolAddress(&p_x16, g_x16);   cudaGetSymbolAddress(&p_h16, g_h16);
    cudaGetSymbolAddress(&p_w1, g_w1);     cudaGetSymbolAddress(&p_woh, g_woh);
    cudaGetSymbolAddress(&p_wol, g_wol);   cudaGetSymbolAddress(&p_w2th, g_w2th);
    cudaGetSymbolAddress(&p_w2tl, g_w2tl); cudaGetSymbolAddress(&p_w2o, g_w2o);
    cudaGetSymbolAddress(&p_bo2, g_bo2);

    cudaFuncSetAttribute(gemm_h1<0>, cudaFuncAttributeMaxDynamicSharedMemorySize, SMEM_TOTAL);
    cudaFuncSetAttribute(gemm_h1<2>, cudaFuncAttributeMaxDynamicSharedMemorySize, SMEM_TOTAL);
    cudaFuncSetAttribute(gemm_w2o, cudaFuncAttributeMaxDynamicSharedMemorySize, WSMEM);

    // [0] x -> fp16
    convw_kernel<<<(M * HIDDEN / 4 + 255) / 256, 256>>>(x, (__half*)p_x16, M * HIDDEN / 4);
    // [1] W1 -> fp16
    convw_kernel<<<(INNER * HIDDEN / 4 + 255) / 256, 256>>>(W1, (__half*)p_w1, INNER * HIDDEN / 4);
    // [2] Wo -> fp16 hi/lo
    splitx_kernel<<<(HIDDEN * HIDDEN / 4 + 255) / 256, 256>>>(
        Wo, (__half*)p_woh, (__half*)p_wol, HIDDEN * HIDDEN / 4);
    // [3] W2 -> W2^T hi/lo
    transp_split_kernel<<<dim3(INNER / 32, HIDDEN / 32), dim3(32, 8)>>>(
        W2, (__half*)p_w2th, (__half*)p_w2tl);
    // [4] bo2 = Wo@b2 + bo
    bo2_kernel<<<(HIDDEN * 32 + 255) / 256, 256>>>(Wo, b2, bo, (float*)p_bo2);
    // [5] GEMM1: h = relu(x @ W1^T + b1) -> fp16   (profiled launch, -s 5)
    gemm_h1<0><<<dim3(INNER / BN, M / BM), 256, SMEM_TOTAL>>>(
        (const __half*)p_x16, (const __half*)p_w1, b1,
        nullptr, (__half*)p_h16, INNER, HIDDEN);
    // [6] W2o = Wo @ W2 (3-pass accurate) -> fp16
    gemm_w2o<<<dim3(INNER / BN, HIDDEN / BM), 256, WSMEM>>>(
        (const __half*)p_woh, (const __half*)p_wol,
        (const __half*)p_w2th, (const __half*)p_w2tl,
        (__half*)p_w2o, INNER, HIDDEN);
    // [7] out = h @ W2o^T + bo2 -> fp32
    gemm_h1<2><<<dim3(HIDDEN / BN, M / BM), 256, SMEM_TOTAL>>>(
        (const __half*)p_h16, (const __half*)p_w2o, (const float*)p_bo2,
        out, nullptr, HIDDEN, INNER);
    // [8] LayerNorm in place
    ln_kernel<<<M, 256>>>(out, gamma, beta);
}

// round 7
// speedup vs baseline: 2.8998x; 1.1178x over previous
#include <cuda_runtime.h>
#include <cuda_fp16.h>
#include <stdint.h>

#define HIDDEN 768
#define INNER  512
#define MAXM   32768

// ---- main GEMM tiles: CTA 128x128, 4 warps (2x2 of 64x64), BK=64, 3-stage, 2 CTAs/SM ----
#define BM 128
#define BN 128
#define BK 64
#define ASTR 144                    // bytes per K-row (128 data + 16 pad)
#define STG_A (BM * ASTR)           // 18432
#define STG_B (BN * ASTR)           // 18432
#define STGB (STG_A + STG_B)        // 36864
#define SMEM_TOTAL (3 * STGB)       // 110592 -> 2 CTAs/SM

// ---- w2o GEMM tiles (BK=32 legacy layout, 256 threads) ----
#define WASTR 80
#define WSTG_A (128 * WASTR)        // 10240
#define WSTG_B (256 * WASTR)        // 20480
#define WSTG (2 * WSTG_A + 2 * WSTG_B)  // 61440
#define WSMEM (2 * WSTG)

// ---------------- device scratch (allocation-free rule) ----------------
__device__ __half g_x16[(size_t)MAXM * HIDDEN];
__device__ __half g_h16[(size_t)MAXM * INNER];
__device__ __half g_w1[INNER * HIDDEN];
__device__ __half g_woh[HIDDEN * HIDDEN];
__device__ __half g_wol[HIDDEN * HIDDEN];
__device__ __half g_w2th[INNER * HIDDEN];
__device__ __half g_w2tl[INNER * HIDDEN];
__device__ __half g_w2o[HIDDEN * INNER];    // fused weight (Wo@W2) fp16 [768,512]
__device__ float  g_bo2[HIDDEN];            // fused bias Wo@b2 + bo

// ---------------- helpers ----------------
__device__ __forceinline__ uint32_t s2u(const void* p) {
    uint32_t a;
    asm("{ .reg .u64 t; cvta.to.shared.u64 t, %1; cvt.u32.u64 %0, t; }" : "=r"(a) : "l"(p));
    return a;
}

__device__ __forceinline__ void ldsm4(uint32_t& d0, uint32_t& d1, uint32_t& d2, uint32_t& d3,
                                      uint32_t addr) {
    asm volatile("ldmatrix.sync.aligned.m8n8.x4.shared.b16 {%0,%1,%2,%3}, [%4];"
                 : "=r"(d0), "=r"(d1), "=r"(d2), "=r"(d3) : "r"(addr));
}

__device__ __forceinline__ void mma_h(float c[4], const uint32_t a[4], const uint32_t b[2]) {
    asm volatile(
        "mma.sync.aligned.m16n8k16.row.col.f32.f16.f16.f32 "
        "{%0,%1,%2,%3}, {%4,%5,%6,%7}, {%8,%9}, {%0,%1,%2,%3};"
        : "+f"(c[0]), "+f"(c[1]), "+f"(c[2]), "+f"(c[3])
        : "r"(a[0]), "r"(a[1]), "r"(a[2]), "r"(a[3]), "r"(b[0]), "r"(b[1]));
}

__device__ __forceinline__ void cpa(uint32_t dst, const void* src) {
    asm volatile("cp.async.cg.shared.global [%0], [%1], 16;" :: "r"(dst), "l"(src));
}
__device__ __forceinline__ void cp_commit() { asm volatile("cp.async.commit_group;"); }
template <int N> __device__ __forceinline__ void cp_wait() {
    asm volatile("cp.async.wait_group %0;" :: "n"(N));
}

// ---------------- conversions ----------------
// fp32 -> single fp16 (x, W1)
__global__ void convw_kernel(const float* __restrict__ w, __half* __restrict__ o, int n4) {
    int i = blockIdx.x * blockDim.x + threadIdx.x;
    if (i >= n4) return;
    float4 v = *reinterpret_cast<const float4*>(w + (size_t)i * 4);
    reinterpret_cast<__half2*>(o)[2 * i]     = __floats2half2_rn(v.x, v.y);
    reinterpret_cast<__half2*>(o)[2 * i + 1] = __floats2half2_rn(v.z, v.w);
}

// fp32 -> fp16 hi/lo pair (Wo, for accurate W2o precompute)
__global__ void splitx_kernel(const float* __restrict__ x,
                              __half* __restrict__ hi, __half* __restrict__ lo, int n4) {
    int i = blockIdx.x * blockDim.x + threadIdx.x;
    if (i >= n4) return;
    float4 v = *reinterpret_cast<const float4*>(x + (size_t)i * 4);
    __half2 h01 = __floats2half2_rn(v.x, v.y);
    __half2 h23 = __floats2half2_rn(v.z, v.w);
    __half2 l01 = __floats2half2_rn(v.x - __low2float(h01), v.y - __high2float(h01));
    __half2 l23 = __floats2half2_rn(v.z - __low2float(h23), v.w - __high2float(h23));
    reinterpret_cast<__half2*>(hi)[2 * i]     = h01;
    reinterpret_cast<__half2*>(hi)[2 * i + 1] = h23;
    reinterpret_cast<__half2*>(lo)[2 * i]     = l01;
    reinterpret_cast<__half2*>(lo)[2 * i + 1] = l23;
}

// W2[d,i] ([768,512] fp32) -> W2^T hi/lo fp16 [i,d] = [512,768]
__global__ void transp_split_kernel(const float* __restrict__ w2,
                                    __half* __restrict__ th, __half* __restrict__ tl) {
    __shared__ float tile[32][33];
    const int i0 = blockIdx.x * 32, d0 = blockIdx.y * 32;
    const int tx = threadIdx.x, ty = threadIdx.y;  // (32, 8)
#pragma unroll
    for (int r = 0; r < 4; r++) {
        int d = d0 + ty + r * 8;
        tile[ty + r * 8][tx] = w2[(size_t)d * INNER + i0 + tx];
    }
    __syncthreads();
#pragma unroll
    for (int r = 0; r < 4; r++) {
        int i = i0 + ty + r * 8;
        float v = tile[tx][ty + r * 8];
        __half h = __float2half_rn(v);
        th[(size_t)i * HIDDEN + d0 + tx] = h;
        tl[(size_t)i * HIDDEN + d0 + tx] = __float2half_rn(v - __half2float(h));
    }
}

// bo2[e] = bo[e] + sum_d Wo[e,d] * b2[d]
__global__ void bo2_kernel(const float* __restrict__ Wo, const float* __restrict__ b2,
                           const float* __restrict__ bo, float* __restrict__ bo2) {
    const int warp = (blockIdx.x * blockDim.x + threadIdx.x) >> 5;
    const int lane = threadIdx.x & 31;
    if (warp >= HIDDEN) return;
    float s = 0.f;
    for (int d = lane; d < HIDDEN; d += 32) s += Wo[(size_t)warp * HIDDEN + d] * b2[d];
#pragma unroll
    for (int o = 16; o > 0; o >>= 1) s += __shfl_xor_sync(0xffffffffu, s, o);
    if (lane == 0) bo2[warp] = s + bo[warp];
}

// ---------------- accurate 3-pass GEMM: W2o = Wo @ W2 -> fp16 (256 thr, 128x256 tile) ----------------
__global__ void __launch_bounds__(256, 1)
gemm_w2o(const __half* __restrict__ Ah, const __half* __restrict__ Al,
         const __half* __restrict__ Bh, const __half* __restrict__ Bl,
         __half* __restrict__ C, int N, int K) {
    extern __shared__ __align__(128) char smem[];
    const uint32_t sb = s2u(smem);
    const int tid = threadIdx.x, lane = tid & 31, warp = tid >> 5;
    const int m0 = blockIdx.y * 128, n0 = blockIdx.x * 256;
    const int wm = (warp >> 2) * 64, wn = (warp & 3) * 64;
    const __half* Agh = Ah + (size_t)m0 * K;
    const __half* Agl = Al + (size_t)m0 * K;
    const __half* Bgh = Bh + (size_t)n0 * K;
    const __half* Bgl = Bl + (size_t)n0 * K;
    const int T = K / 32;

    float acc[4][8][4];
#pragma unroll
    for (int i = 0; i < 4; i++)
#pragma unroll
        for (int j = 0; j < 8; j++)
#pragma unroll
            for (int r = 0; r < 4; r++) acc[i][j][r] = 0.f;

    auto load_stage = [&](int s, int t) {
        const uint32_t so = sb + s * WSTG;
        const int k0 = t * 32;
#pragma unroll
        for (int it = 0; it < 2; it++) {
            int idx = tid + it * 256;
            int r = idx >> 2, c = idx & 3;
            cpa(so + r * WASTR + c * 16, (const char*)(Agh + (size_t)r * K + k0) + c * 16);
            cpa(so + WSTG_A + r * WASTR + c * 16, (const char*)(Agl + (size_t)r * K + k0) + c * 16);
        }
#pragma unroll
        for (int it = 0; it < 4; it++) {
            int idx = tid + it * 256;
            int r = idx >> 2, c = idx & 3;
            cpa(so + 2 * WSTG_A + r * WASTR + c * 16,
                (const char*)(Bgh + (size_t)r * K + k0) + c * 16);
            cpa(so + 2 * WSTG_A + WSTG_B + r * WASTR + c * 16,
                (const char*)(Bgl + (size_t)r * K + k0) + c * 16);
        }
        cp_commit();
    };

    const int a_row = wm + ((lane >> 3) & 1) * 8 + (lane & 7);
    const int a_kh  = ((lane >> 4) & 1) * 8;
    const int b_row = wn + ((lane >> 4) & 1) * 8 + (lane & 7);
    const int b_kh  = ((lane >> 3) & 1) * 8;

    load_stage(0, 0);
    for (int t = 0; t < T; t++) {
        if (t + 1 < T) load_stage((t + 1) & 1, t + 1);
        if (t + 1 < T) cp_wait<1>(); else cp_wait<0>();
        __syncthreads();
        const uint32_t so = sb + (t & 1) * WSTG;
#pragma unroll
        for (int kk = 0; kk < 2; kk++) {
            const int kc2 = (kk * 16 + a_kh) * 2;
            const int kb2 = (kk * 16 + b_kh) * 2;
            uint32_t ah[4][4], al[4][4], b[8][2];
#pragma unroll
            for (int j2 = 0; j2 < 4; j2++)
                ldsm4(b[2 * j2][0], b[2 * j2][1], b[2 * j2 + 1][0], b[2 * j2 + 1][1],
                      so + 2 * WSTG_A + (b_row + j2 * 16) * WASTR + kb2);
#pragma unroll
            for (int i = 0; i < 4; i++)
                ldsm4(ah[i][0], ah[i][1], ah[i][2], ah[i][3],
                      so + (a_row + i * 16) * WASTR + kc2);
#pragma unroll
            for (int i = 0; i < 4; i++)
#pragma unroll
                for (int j = 0; j < 8; j++) mma_h(acc[i][j], ah[i], b[j]);
#pragma unroll
            for (int i = 0; i < 4; i++)
                ldsm4(al[i][0], al[i][1], al[i][2], al[i][3],
                      so + WSTG_A + (a_row + i * 16) * WASTR + kc2);
#pragma unroll
            for (int i = 0; i < 4; i++)
#pragma unroll
                for (int j = 0; j < 8; j++) mma_h(acc[i][j], al[i], b[j]);
#pragma unroll
            for (int j2 = 0; j2 < 4; j2++)
                ldsm4(b[2 * j2][0], b[2 * j2][1], b[2 * j2 + 1][0], b[2 * j2 + 1][1],
                      so + 2 * WSTG_A + WSTG_B + (b_row + j2 * 16) * WASTR + kb2);
#pragma unroll
            for (int i = 0; i < 4; i++)
#pragma unroll
                for (int j = 0; j < 8; j++) mma_h(acc[i][j], ah[i], b[j]);
        }
        __syncthreads();
    }

    const int erow = lane >> 2, ecol = (lane & 3) * 2;
#pragma unroll
    for (int i = 0; i < 4; i++) {
        const int r0 = m0 + wm + i * 16 + erow;
#pragma unroll
        for (int j = 0; j < 8; j++) {
            const int col = n0 + wn + j * 8 + ecol;
            *reinterpret_cast<__half2*>(C + (size_t)r0 * N + col) =
                __floats2half2_rn(acc[i][j][0], acc[i][j][1]);
            *reinterpret_cast<__half2*>(C + (size_t)(r0 + 8) * N + col) =
                __floats2half2_rn(acc[i][j][2], acc[i][j][3]);
        }
    }
}

// ---------------- main single-pass GEMM: C[M,N] = A[M,K] @ B[N,K]^T + bias ----------------
// CTA 128x128, 4 warps (2x2 of 64x64), BK=64, 3-stage cp.async, 2 CTAs/SM.
// EPI: 0 = relu + fp16 out, 2 = fp32 out
template <int EPI>
__global__ void __launch_bounds__(128, 2)
gemm_h1(const __half* __restrict__ A, const __half* __restrict__ B,
        const float* __restrict__ bias,
        float* __restrict__ Co, __half* __restrict__ Ch, int N, int K) {
    extern __shared__ __align__(128) char smem[];
    const uint32_t sb = s2u(smem);
    const int tid = threadIdx.x, lane = tid & 31, warp = tid >> 5;
    const int m0 = blockIdx.y * BM, n0 = blockIdx.x * BN;
    const int wm = (warp >> 1) * 64;   // 2 warp rows
    const int wn = (warp & 1) * 64;    // 2 warp cols

    const __half* Ag = A + (size_t)m0 * K;
    const __half* Bg = B + (size_t)n0 * K;
    const int T = K / BK;

    float acc[4][8][4];
#pragma unroll
    for (int i = 0; i < 4; i++)
#pragma unroll
        for (int j = 0; j < 8; j++)
#pragma unroll
            for (int r = 0; r < 4; r++) acc[i][j][r] = 0.f;

    auto load_stage = [&](int s, int t) {
        const uint32_t so = sb + s * STGB;
        const int k0 = t * BK;
#pragma unroll
        for (int it = 0; it < 8; it++) {     // A: 128 rows x 8 chunks of 16B
            int idx = tid + it * 128;
            int r = idx >> 3, c = idx & 7;
            cpa(so + r * ASTR + c * 16, (const char*)(Ag + (size_t)r * K + k0) + c * 16);
        }
#pragma unroll
        for (int it = 0; it < 8; it++) {     // B: 128 rows x 8 chunks
            int idx = tid + it * 128;
            int r = idx >> 3, c = idx & 7;
            cpa(so + STG_A + r * ASTR + c * 16, (const char*)(Bg + (size_t)r * K + k0) + c * 16);
        }
        cp_commit();
    };

    load_stage(0, 0);
    load_stage(1, 1);

    const int a_row = wm + ((lane >> 3) & 1) * 8 + (lane & 7);
    const int a_kh  = ((lane >> 4) & 1) * 8;
    const int b_row = wn + ((lane >> 4) & 1) * 8 + (lane & 7);
    const int b_kh  = ((lane >> 3) & 1) * 8;

    for (int t = 0; t < T; t++) {
        if (t + 1 < T) cp_wait<1>(); else cp_wait<0>();
        __syncthreads();
        if (t + 2 < T) load_stage((t + 2) % 3, t + 2);

        const uint32_t so = sb + (t % 3) * STGB;
#pragma unroll
        for (int kk = 0; kk < 4; kk++) {
            const int ka2 = (kk * 16 + a_kh) * 2;
            const int kb2 = (kk * 16 + b_kh) * 2;
            uint32_t b[8][2];
#pragma unroll
            for (int j2 = 0; j2 < 4; j2++)
                ldsm4(b[2 * j2][0], b[2 * j2][1], b[2 * j2 + 1][0], b[2 * j2 + 1][1],
                      so + STG_A + (b_row + j2 * 16) * ASTR + kb2);
            uint32_t a[4][4];
#pragma unroll
            for (int i = 0; i < 4; i++)
                ldsm4(a[i][0], a[i][1], a[i][2], a[i][3],
                      so + (a_row + i * 16) * ASTR + ka2);
#pragma unroll
            for (int i = 0; i < 4; i++)
#pragma unroll
                for (int j = 0; j < 8; j++) mma_h(acc[i][j], a[i], b[j]);
        }
    }

    const int erow = lane >> 2;
    const int ecol = (lane & 3) * 2;
#pragma unroll
    for (int i = 0; i < 4; i++) {
        const int r0 = m0 + wm + i * 16 + erow;
#pragma unroll
        for (int j = 0; j < 8; j++) {
            const int col = n0 + wn + j * 8 + ecol;
            const float bv0 = __ldg(bias + col);
            const float bv1 = __ldg(bias + col + 1);
            float v0 = acc[i][j][0] + bv0;
            float v1 = acc[i][j][1] + bv1;
            float v2 = acc[i][j][2] + bv0;
            float v3 = acc[i][j][3] + bv1;
            if (EPI == 0) {
                v0 = fmaxf(v0, 0.f); v1 = fmaxf(v1, 0.f);
                v2 = fmaxf(v2, 0.f); v3 = fmaxf(v3, 0.f);
                *reinterpret_cast<__half2*>(Ch + (size_t)r0 * N + col) = __floats2half2_rn(v0, v1);
                *reinterpret_cast<__half2*>(Ch + (size_t)(r0 + 8) * N + col) = __floats2half2_rn(v2, v3);
            } else {
                *reinterpret_cast<float2*>(Co + (size_t)r0 * N + col) = make_float2(v0, v1);
                *reinterpret_cast<float2*>(Co + (size_t)(r0 + 8) * N + col) = make_float2(v2, v3);
            }
        }
    }
}

// ---------------- LayerNorm over rows of 768 (vectorized float4, 192 thr/row) ----------------
__global__ void __launch_bounds__(192)
ln_kernel(float* __restrict__ out,
          const float* __restrict__ gamma,
          const float* __restrict__ beta) {
    const int row = blockIdx.x;
    float* p = out + (size_t)row * HIDDEN;
    const int c4 = threadIdx.x * 4;
    float4 v = *reinterpret_cast<const float4*>(p + c4);
    float s = v.x + v.y + v.z + v.w;
    float s2 = v.x * v.x + v.y * v.y + v.z * v.z + v.w * v.w;
#pragma unroll
    for (int o = 16; o > 0; o >>= 1) {
        s += __shfl_xor_sync(0xffffffffu, s, o);
        s2 += __shfl_xor_sync(0xffffffffu, s2, o);
    }
    __shared__ float ss[6], ss2[6];
    if ((threadIdx.x & 31) == 0) {
        ss[threadIdx.x >> 5] = s;
        ss2[threadIdx.x >> 5] = s2;
    }
    __syncthreads();
    float st = 0.f, st2 = 0.f;
#pragma unroll
    for (int i = 0; i < 6; i++) { st += ss[i]; st2 += ss2[i]; }
    const float mu = st * (1.0f / HIDDEN);
    const float var = st2 * (1.0f / HIDDEN) - mu * mu;
    const float inv = rsqrtf(var + 1e-5f);
    const float4 g = *reinterpret_cast<const float4*>(gamma + c4);
    const float4 bb = *reinterpret_cast<const float4*>(beta + c4);
    float4 o;
    o.x = (v.x - mu) * inv * g.x + bb.x;
    o.y = (v.y - mu) * inv * g.y + bb.y;
    o.z = (v.z - mu) * inv * g.z + bb.z;
    o.w = (v.w - mu) * inv * g.w + bb.w;
    *reinterpret_cast<float4*>(p + c4) = o;
}

// ---------------- launch ----------------
extern "C" void kernel_launch(void* const* d_in, const int* in_sizes, int n_in,
                              void* d_out, int out_size) {
    const float* x     = (const float*)d_in[0];
    const float* W1    = (const float*)d_in[1];
    const float* b1    = (const float*)d_in[2];
    const float* W2    = (const float*)d_in[3];
    const float* b2    = (const float*)d_in[4];
    const float* Wo    = (const float*)d_in[5];
    const float* bo    = (const float*)d_in[6];
    const float* gamma = (const float*)d_in[7];
    const float* beta  = (const float*)d_in[8];
    float* out = (float*)d_out;
    (void)n_in; (void)out_size;

    const int M = in_sizes[0] / HIDDEN;  // 32768

    void *p_x16, *p_h16, *p_w1, *p_woh, *p_wol, *p_w2th, *p_w2tl, *p_w2o, *p_bo2;
    cudaGetSymbolAddress(&p_x16, g_x16);   cudaGetSymbolAddress(&p_h16, g_h16);
    cudaGetSymbolAddress(&p_w1, g_w1);     cudaGetSymbolAddress(&p_woh, g_woh);
    cudaGetSymbolAddress(&p_wol, g_wol);   cudaGetSymbolAddress(&p_w2th, g_w2th);
    cudaGetSymbolAddress(&p_w2tl, g_w2tl); cudaGetSymbolAddress(&p_w2o, g_w2o);
    cudaGetSymbolAddress(&p_bo2, g_bo2);

    cudaFuncSetAttribute(gemm_h1<0>, cudaFuncAttributeMaxDynamicSharedMemorySize, SMEM_TOTAL);
    cudaFuncSetAttribute(gemm_h1<2>, cudaFuncAttributeMaxDynamicSharedMemorySize, SMEM_TOTAL);
    cudaFuncSetAttribute(gemm_w2o, cudaFuncAttributeMaxDynamicSharedMemorySize, WSMEM);

    // [0] x -> fp16
    convw_kernel<<<(M * HIDDEN / 4 + 255) / 256, 256>>>(x, (__half*)p_x16, M * HIDDEN / 4);
    // [1] W1 -> fp16
    convw_kernel<<<(INNER * HIDDEN / 4 + 255) / 256, 256>>>(W1, (__half*)p_w1, INNER * HIDDEN / 4);
    // [2] Wo -> fp16 hi/lo
    splitx_kernel<<<(HIDDEN * HIDDEN / 4 + 255) / 256, 256>>>(
        Wo, (__half*)p_woh, (__half*)p_wol, HIDDEN * HIDDEN / 4);
    // [3] W2 -> W2^T hi/lo
    transp_split_kernel<<<dim3(INNER / 32, HIDDEN / 32), dim3(32, 8)>>>(
        W2, (__half*)p_w2th, (__half*)p_w2tl);
    // [4] bo2 = Wo@b2 + bo
    bo2_kernel<<<(HIDDEN * 32 + 255) / 256, 256>>>(Wo, b2, bo, (float*)p_bo2);
    // [5] GEMM1: h = relu(x @ W1^T + b1) -> fp16   (profiled launch, -s 5)
    gemm_h1<0><<<dim3(INNER / BN, M / BM), 128, SMEM_TOTAL>>>(
        (const __half*)p_x16, (const __half*)p_w1, b1,
        nullptr, (__half*)p_h16, INNER, HIDDEN);
    // [6] W2o = Wo @ W2 (3-pass accurate) -> fp16
    gemm_w2o<<<dim3(INNER / 256, HIDDEN / 128), 256, WSMEM>>>(
        (const __half*)p_woh, (const __half*)p_wol,
        (const __half*)p_w2th, (const __half*)p_w2tl,
        (__half*)p_w2o, INNER, HIDDEN);
    // [7] out = h @ W2o^T + bo2 -> fp32
    gemm_h1<2><<<dim3(HIDDEN / BN, M / BM), 128, SMEM_TOTAL>>>(
        (const __half*)p_h16, (const __half*)p_w2o, (const float*)p_bo2,
        out, nullptr, HIDDEN, INNER);
    // [8] LayerNorm in place
    ln_kernel<<<M, 192>>>(out, gamma, beta);
}